// round 10
// baseline (speedup 1.0000x reference)
#include <cuda_runtime.h>
#include <cuda_bf16.h>
#include <math.h>
#include <stdint.h>

// Problem constants
#define NN 100000      // nodes
#define EE 500000      // edges
#define RR 8           // relations
#define DD 128         // hidden
#define KT 1152        // Wt rows: R*D (relations) + D (root)
#define NPAIR (NN * RR)                     // 800000 (node, rel) pairs
#define TM 64                               // GEMM tile M
#define MAXBLK ((NPAIR + RR * (TM - 1) + TM - 1) / TM)   // max 64-row blocks after padding
#define NVROW (MAXBLK * TM)
#define ROOTBLK ((NN + TM - 1) / TM)        // 1563

// -------- scratch (device globals; no allocation allowed) --------
__device__ __nv_bfloat16 g_xhi[(size_t)NN * DD];
__device__ __nv_bfloat16 g_xlo[(size_t)NN * DD];
__device__ __nv_bfloat16 g_wthi[2 * (size_t)KT * DD];   // both layers
__device__ __nv_bfloat16 g_wtlo[2 * (size_t)KT * DD];
__device__ float g_out[(size_t)NN * DD];
__device__ float g_inv[NPAIR];       // 1/indeg(dst,rel)
__device__ int   g_cnt[NPAIR];       // in-degree per (dst,rel)
__device__ int   g_scnt[NPAIR];      // out-degree per (src,rel)
__device__ int   g_pos[NPAIR];       // (src,rel) -> virtual row
__device__ int   g_vnode[NVROW];     // virtual row -> node (-1 = pad)
__device__ int   g_relnz[RR];
__device__ int   g_fill[RR];
__device__ int   g_base[RR + 1];
__device__ int   g_nblk;             // active blocks
__device__ int   g_blockrel[MAXBLK];
__device__ int   g_bins[MAXBLK];
__device__ int   g_ptr[MAXBLK + 1];
__device__ int   g_cur[MAXBLK];
__device__ int   g_els[EE];          // sorted edges: local src row (pos % TM)
__device__ int   g_ed[EE];           // sorted edges: dst
__device__ float g_einv[EE];         // sorted edges: 1/cnt(dst,rel)

// ---------------- helpers ----------------
__device__ __forceinline__ uint32_t saddr(const void* p) {
    return (uint32_t)__cvta_generic_to_shared(p);
}
__device__ __forceinline__ void ldsm_x4(uint32_t* r, uint32_t addr) {
    asm volatile("ldmatrix.sync.aligned.m8n8.x4.shared.b16 {%0,%1,%2,%3}, [%4];"
                 : "=r"(r[0]), "=r"(r[1]), "=r"(r[2]), "=r"(r[3]) : "r"(addr));
}
__device__ __forceinline__ void mma_bf16(float* c, const uint32_t* a, const uint32_t* b) {
    asm volatile("mma.sync.aligned.m16n8k16.row.col.f32.bf16.bf16.f32 "
                 "{%0,%1,%2,%3}, {%4,%5,%6,%7}, {%8,%9}, {%0,%1,%2,%3};"
                 : "+f"(c[0]), "+f"(c[1]), "+f"(c[2]), "+f"(c[3])
                 : "r"(a[0]), "r"(a[1]), "r"(a[2]), "r"(a[3]), "r"(b[0]), "r"(b[1]));
}
__device__ __forceinline__ void split2(float v, __nv_bfloat16& h, __nv_bfloat16& l) {
    h = __float2bfloat16(v);
    l = __float2bfloat16(v - __bfloat162float(h));
}
__device__ __forceinline__ void red_add4(float* p, float4 v) {
    asm volatile("red.global.add.v4.f32 [%0], {%1, %2, %3, %4};"
                 :: "l"(p), "f"(v.x), "f"(v.y), "f"(v.z), "f"(v.w) : "memory");
}
__device__ __forceinline__ void red_add2(float* p, float2 v) {
    asm volatile("red.global.add.v2.f32 [%0], {%1, %2};"
                 :: "l"(p), "f"(v.x), "f"(v.y) : "memory");
}

// ---------------- fused prep: gather_split | wsplit(L1) | wsplit(L2) | hist2 ----------------
#define P_GATHER (NN * 32 / 256)                 // 12500 blocks
#define P_WS     ((KT * DD) / 256)               // 576 blocks each
#define P_HIST   ((EE + 255) / 256)              // 1954 blocks
#define PREP1_GRID (P_GATHER + 2 * P_WS + P_HIST)

__global__ void k_prep1(const int* __restrict__ ids, const float* __restrict__ emb,
                        const float* __restrict__ W1, const float* __restrict__ root1,
                        const float* __restrict__ W2, const float* __restrict__ root2,
                        const int* __restrict__ ei, const int* __restrict__ et) {
    int b = blockIdx.x;
    if (b < P_GATHER) {
        int t = b * 256 + threadIdx.x;
        int n = t >> 5, l4 = (t & 31) * 4;
        if (n >= NN) return;
        float4 v = *((const float4*)(emb + (size_t)ids[n] * DD + l4));
        __nv_bfloat16 h0, h1, h2, h3, l0, l1, l2, l3;
        split2(v.x, h0, l0); split2(v.y, h1, l1); split2(v.z, h2, l2); split2(v.w, h3, l3);
        __nv_bfloat162* ph = (__nv_bfloat162*)(g_xhi + (size_t)n * DD + l4);
        __nv_bfloat162* pl = (__nv_bfloat162*)(g_xlo + (size_t)n * DD + l4);
        ph[0] = __nv_bfloat162{h0, h1}; ph[1] = __nv_bfloat162{h2, h3};
        pl[0] = __nv_bfloat162{l0, l1}; pl[1] = __nv_bfloat162{l2, l3};
        return;
    }
    b -= P_GATHER;
    if (b < 2 * P_WS) {
        int layer = b >= P_WS;
        int t = (b - layer * P_WS) * 256 + threadIdx.x;
        const float* W     = layer ? W2 : W1;
        const float* rootM = layer ? root2 : root1;
        int loff = layer * KT * DD;
        int c = t >> 7, d = t & 127;
        float v;
        if (c < RR * DD) {
            int r = c >> 7, f = c & 127;
            v = W[((size_t)r * DD + d) * DD + f];
        } else {
            v = rootM[(size_t)d * DD + (c - RR * DD)];
        }
        __nv_bfloat16 h, l; split2(v, h, l);
        g_wthi[loff + t] = h; g_wtlo[loff + t] = l;
        return;
    }
    b -= 2 * P_WS;
    {
        int e = b * 256 + threadIdx.x;
        if (e >= EE) return;
        int src = ei[e], dst = ei[EE + e], r = et[e];
        atomicAdd(&g_cnt[dst * RR + r], 1);
        atomicAdd(&g_scnt[src * RR + r], 1);
    }
}

// inv + per-relation live-pair counts (block-aggregated atomics)
__global__ void k_inv_relnz() {
    __shared__ int c[RR];
    if (threadIdx.x < RR) c[threadIdx.x] = 0;
    __syncthreads();
    int t = blockIdx.x * blockDim.x + threadIdx.x;
    if (t < NPAIR) {
        int n = g_cnt[t];
        g_inv[t] = n > 0 ? 1.0f / (float)n : 0.0f;
        if (g_scnt[t] > 0) atomicAdd(&c[t & (RR - 1)], 1);
    }
    __syncthreads();
    if (threadIdx.x < RR && c[threadIdx.x] > 0) atomicAdd(&g_relnz[threadIdx.x], c[threadIdx.x]);
}

// bases (serial, 8 iters) + blockrel fill, single block
__global__ void k_bases_blockrel() {
    __shared__ int sbase[RR + 1];
    if (threadIdx.x == 0) {
        int b = 0;
        g_base[0] = 0; sbase[0] = 0;
        for (int r = 0; r < RR; r++) {
            b += (g_relnz[r] + TM - 1) & ~(TM - 1);
            g_base[r + 1] = b; sbase[r + 1] = b;
        }
        g_nblk = b / TM;
    }
    __syncthreads();
    for (int i = threadIdx.x; i < MAXBLK; i += blockDim.x) {
        int row = i * TM, rel = 0;
        for (int r = 0; r < RR; r++)
            if (row >= sbase[r] && row < sbase[r + 1]) rel = r;
        g_blockrel[i] = rel;
    }
}

// compact live pairs into virtual rows + per-block edge bin counts.
// Block-aggregated g_fill atomics: smem rank within block, ONE global
// atomicAdd per (block, relation). Within-relation order is arbitrary.
__global__ void k_compact() {
    __shared__ int cnt[RR];
    __shared__ int basep[RR];
    int t = blockIdx.x * 256 + threadIdx.x;
    if (threadIdx.x < RR) cnt[threadIdx.x] = 0;
    __syncthreads();
    int sc = 0, rel = 0, rank = 0, node = 0;
    bool live = false;
    if (t < NPAIR) {
        sc = g_scnt[t];
        if (sc > 0) {
            live = true;
            node = t >> 3;              // RR == 8
            rel  = t & 7;
            rank = atomicAdd(&cnt[rel], 1);
        }
    }
    __syncthreads();
    if (threadIdx.x < RR)
        basep[threadIdx.x] = cnt[threadIdx.x] ? atomicAdd(&g_fill[threadIdx.x], cnt[threadIdx.x]) : 0;
    __syncthreads();
    if (live) {
        int pos = g_base[rel] + basep[rel] + rank;
        g_vnode[pos] = node;
        g_pos[t] = pos;
        atomicAdd(&g_bins[pos / TM], sc);   // bin size = sum of out-degrees
    }
}

// single-block exclusive scan over MAXBLK bins
__global__ void k_scan() {
    __shared__ int wsum[32];
    const int tid = threadIdx.x;
    const int per = (MAXBLK + 1023) / 1024;
    int base = tid * per;
    int loc[16]; int s = 0;
    for (int i = 0; i < per; i++) {
        int idx = base + i;
        int v = (idx < MAXBLK) ? g_bins[idx] : 0;
        loc[i] = s; s += v;
    }
    int lane = tid & 31, wid = tid >> 5;
    int x = s;
    for (int d = 1; d < 32; d <<= 1) {
        int y = __shfl_up_sync(0xffffffffu, x, d);
        if (lane >= d) x += y;
    }
    if (lane == 31) wsum[wid] = x;
    __syncthreads();
    if (wid == 0) {
        int y = wsum[lane];
        for (int d = 1; d < 32; d <<= 1) {
            int z = __shfl_up_sync(0xffffffffu, y, d);
            if (lane >= d) y += z;
        }
        wsum[lane] = y;
    }
    __syncthreads();
    int excl = x - s + (wid > 0 ? wsum[wid - 1] : 0);
    for (int i = 0; i < per; i++) {
        int idx = base + i;
        if (idx < MAXBLK) { int p = excl + loc[i]; g_ptr[idx] = p; g_cur[idx] = p; }
    }
    if (tid == 1023) g_ptr[MAXBLK] = excl + s;
}

__global__ void k_eperm(const int* __restrict__ ei, const int* __restrict__ et) {
    int e = blockIdx.x * blockDim.x + threadIdx.x;
    if (e >= EE) return;
    int src = ei[e], dst = ei[EE + e], r = et[e];
    int pos = g_pos[src * RR + r];
    int i = atomicAdd(&g_cur[pos / TM], 1);
    g_els[i]  = pos % TM;
    g_ed[i]   = dst;
    g_einv[i] = g_inv[dst * RR + r];
}

// ---------------- combined GEMM (rel blocks first, then root blocks) ----------------
// g_out MUST be zeroed before this launch; BOTH paths accumulate via red.add,
// making rel/root CTA interleaving order-independent.
#define PADK 136
#define GSM_AH 0
#define GSM_AL 17408
#define GSM_BH 34816
#define GSM_BL 69632
#define GSM_TOTAL 104448     // per-CTA dynamic smem; 2 CTAs/SM

// MMA core: 64(M) x 128(N) x 128(K), warps 2(M) x 4(N), warp tile 32x32
#define MMA_CORE(Ah, Al, Bh, Bl, acc)                                              \
    {                                                                              \
        _Pragma("unroll")                                                          \
        for (int ks = 0; ks < 8; ks++) {                                           \
            const int k0 = ks * 16;                                                \
            uint32_t ah[2][4], al[2][4];                                           \
            _Pragma("unroll")                                                      \
            for (int mf = 0; mf < 2; mf++) {                                       \
                ldsm_x4(ah[mf], saddr(Ah + (a_row + mf * 16) * PADK + k0 + a_koff));\
                ldsm_x4(al[mf], saddr(Al + (a_row + mf * 16) * PADK + k0 + a_koff));\
            }                                                                      \
            _Pragma("unroll")                                                      \
            for (int np = 0; np < 2; np++) {                                       \
                uint32_t bh[4], bl[4];                                             \
                ldsm_x4(bh, saddr(Bh + (b_nrow + np * 16) * PADK + k0 + b_koff));  \
                ldsm_x4(bl, saddr(Bl + (b_nrow + np * 16) * PADK + k0 + b_koff));  \
                _Pragma("unroll")                                                  \
                for (int sub = 0; sub < 2; sub++) {                                \
                    uint32_t bfh[2] = { bh[sub], bh[sub + 2] };                    \
                    uint32_t bfl[2] = { bl[sub], bl[sub + 2] };                    \
                    _Pragma("unroll")                                              \
                    for (int mf = 0; mf < 2; mf++) {                               \
                        float* c = acc[mf][np * 2 + sub];                          \
                        mma_bf16(c, ah[mf], bfh);                                  \
                        mma_bf16(c, ah[mf], bfl);                                  \
                        mma_bf16(c, al[mf], bfh);                                  \
                    }                                                              \
                }                                                                  \
            }                                                                      \
        }                                                                          \
    }

__global__ __launch_bounds__(256, 2)
void k_gemm_all(int loff) {
    extern __shared__ char sm[];
    __nv_bfloat16* Ah = (__nv_bfloat16*)(sm + GSM_AH);
    __nv_bfloat16* Al = (__nv_bfloat16*)(sm + GSM_AL);
    __nv_bfloat16* Bh = (__nv_bfloat16*)(sm + GSM_BH);
    __nv_bfloat16* Bl = (__nv_bfloat16*)(sm + GSM_BL);
    float*         hsm = (float*)(sm + GSM_BH);   // aliases B after MMA (rel path)

    const int tid  = threadIdx.x;
    const int lane = tid & 31, warp = tid >> 5;

    const bool isRel = (int)blockIdx.x < MAXBLK;
    if (isRel && (int)blockIdx.x >= g_nblk) return;

    const int brow = isRel ? g_blockrel[blockIdx.x] : RR;   // B row-block in Wt
    const int row0 = isRel ? (int)blockIdx.x * TM : ((int)blockIdx.x - MAXBLK) * TM;

    // ---- load A ----
    for (int v = tid; v < 1024; v += 256) {
        int r = v >> 4, c8 = (v & 15) << 3;
        int node;
        if (isRel) node = g_vnode[row0 + r];
        else       node = (row0 + r < NN) ? row0 + r : -1;
        uint4 h = make_uint4(0, 0, 0, 0), l = make_uint4(0, 0, 0, 0);
        if (node >= 0) {
            h = *(const uint4*)(g_xhi + (size_t)node * DD + c8);
            l = *(const uint4*)(g_xlo + (size_t)node * DD + c8);
        }
        *(uint4*)(Ah + r * PADK + c8) = h;
        *(uint4*)(Al + r * PADK + c8) = l;
    }
    // ---- load B ----
    for (int v = tid; v < 2048; v += 256) {
        int r = v >> 4, c8 = (v & 15) << 3;
        const size_t gofs = (size_t)loff + (size_t)(brow * DD + r) * DD + c8;
        *(uint4*)(Bh + r * PADK + c8) = *(const uint4*)(g_wthi + gofs);
        *(uint4*)(Bl + r * PADK + c8) = *(const uint4*)(g_wtlo + gofs);
    }
    __syncthreads();

    const int wm = warp & 1, wn = warp >> 1;
    const int a_row  = wm * 32 + (lane & 15);
    const int a_koff = (lane >> 4) * 8;
    const int b_nrow = wn * 32 + (lane & 7) + ((lane >> 3) & 1) * 8;
    const int b_koff = (lane >> 4) * 8;

    float acc[2][4][4];
#pragma unroll
    for (int i = 0; i < 2; i++)
#pragma unroll
        for (int j = 0; j < 4; j++)
#pragma unroll
            for (int k = 0; k < 4; k++) acc[i][j][k] = 0.f;

    MMA_CORE(Ah, Al, Bh, Bl, acc)

    if (!isRel) {
        // root path: accumulate into pre-zeroed g_out (race-free vs rel scatter)
#pragma unroll
        for (int mf = 0; mf < 2; mf++) {
#pragma unroll
            for (int nf = 0; nf < 4; nf++) {
                int r = row0 + wm * 32 + mf * 16 + (lane >> 2);
                int c = wn * 32 + nf * 8 + (lane & 3) * 2;
                float* cc = acc[mf][nf];
                if (r < NN)
                    red_add2(g_out + (size_t)r * DD + c, make_float2(cc[0], cc[1]));
                if (r + 8 < NN)
                    red_add2(g_out + (size_t)(r + 8) * DD + c, make_float2(cc[2], cc[3]));
            }
        }
        return;
    }

    __syncthreads();   // all warps done reading B before hsm overwrites it

    // h tile -> smem (aliased over B)
#pragma unroll
    for (int mf = 0; mf < 2; mf++) {
#pragma unroll
        for (int nf = 0; nf < 4; nf++) {
            int r = wm * 32 + mf * 16 + (lane >> 2);
            int c = wn * 32 + nf * 8 + (lane & 3) * 2;
            float* cc = acc[mf][nf];
            *(float2*)(hsm + r * 128 + c)       = make_float2(cc[0], cc[1]);
            *(float2*)(hsm + (r + 8) * 128 + c) = make_float2(cc[2], cc[3]);
        }
    }
    __syncthreads();

    // scatter this block's edges (one warp per edge)
    int s = g_ptr[blockIdx.x], e2 = g_ptr[blockIdx.x + 1];
    for (int i = s + warp; i < e2; i += 8) {
        int   ls  = g_els[i];
        int   dst = g_ed[i];
        float inv = g_einv[i];
        float4 v = *(const float4*)(hsm + ls * 128 + lane * 4);
        v.x *= inv; v.y *= inv; v.z *= inv; v.w *= inv;
        red_add4(g_out + (size_t)dst * DD + lane * 4, v);
    }
}

// ---------------- activations ----------------
// relu + split; ALSO zeroes g_out in the same pass (replaces the L2 memset)
__global__ void k_act_relu(const float* __restrict__ bias) {
    int t = blockIdx.x * blockDim.x + threadIdx.x;
    if (t >= NN * 32) return;
    float4 v = *(const float4*)(g_out + (size_t)t * 4);
    float4 b = __ldg((const float4*)(bias + (t & 31) * 4));
    v.x = fmaxf(v.x + b.x, 0.f); v.y = fmaxf(v.y + b.y, 0.f);
    v.z = fmaxf(v.z + b.z, 0.f); v.w = fmaxf(v.w + b.w, 0.f);
    *(float4*)(g_out + (size_t)t * 4) = make_float4(0.f, 0.f, 0.f, 0.f);
    __nv_bfloat16 h0, h1, h2, h3, l0, l1, l2, l3;
    split2(v.x, h0, l0); split2(v.y, h1, l1); split2(v.z, h2, l2); split2(v.w, h3, l3);
    __nv_bfloat162* ph = (__nv_bfloat162*)(g_xhi + (size_t)t * 4);
    __nv_bfloat162* pl = (__nv_bfloat162*)(g_xlo + (size_t)t * 4);
    ph[0] = __nv_bfloat162{h0, h1}; ph[1] = __nv_bfloat162{h2, h3};
    pl[0] = __nv_bfloat162{l0, l1}; pl[1] = __nv_bfloat162{l2, l3};
}

__global__ void k_sigmoid(const float* __restrict__ bias, float* __restrict__ outp) {
    int t = blockIdx.x * blockDim.x + threadIdx.x;
    if (t >= NN * 32) return;
    float4 v = *(const float4*)(g_out + (size_t)t * 4);
    float4 b = __ldg((const float4*)(bias + (t & 31) * 4));
    v.x = 1.0f / (1.0f + __expf(-(v.x + b.x)));
    v.y = 1.0f / (1.0f + __expf(-(v.y + b.y)));
    v.z = 1.0f / (1.0f + __expf(-(v.z + b.z)));
    v.w = 1.0f / (1.0f + __expf(-(v.w + b.w)));
    *(float4*)(outp + (size_t)t * 4) = v;
}

// ---------------- launch ----------------
extern "C" void kernel_launch(void* const* d_in, const int* in_sizes, int n_in,
                              void* d_out, int out_size) {
    const int*   x_ids = (const int*)  d_in[0];
    const int*   ei    = (const int*)  d_in[1];   // [2, E]: src row then dst row
    const int*   et    = (const int*)  d_in[2];
    const float* emb   = (const float*)d_in[3];
    const float* W1    = (const float*)d_in[4];
    const float* root1 = (const float*)d_in[5];
    const float* b1    = (const float*)d_in[6];
    const float* W2    = (const float*)d_in[7];
    const float* root2 = (const float*)d_in[8];
    const float* b2    = (const float*)d_in[9];
    float*       out   = (float*)d_out;
    (void)in_sizes; (void)n_in; (void)out_size;

    cudaFuncSetAttribute(k_gemm_all, cudaFuncAttributeMaxDynamicSharedMemorySize, GSM_TOTAL);

    void *p_cnt, *p_scnt, *p_relnz, *p_fill, *p_bins, *p_vnode, *p_out;
    cudaGetSymbolAddress(&p_cnt,   g_cnt);
    cudaGetSymbolAddress(&p_scnt,  g_scnt);
    cudaGetSymbolAddress(&p_relnz, g_relnz);
    cudaGetSymbolAddress(&p_fill,  g_fill);
    cudaGetSymbolAddress(&p_bins,  g_bins);
    cudaGetSymbolAddress(&p_vnode, g_vnode);
    cudaGetSymbolAddress(&p_out,   g_out);

    const int T = 256;

    // ---- zero/init (async memsets; g_vnode = 0xFF.. == -1) ----
    cudaMemsetAsync(p_cnt,   0,    NPAIR * sizeof(int));
    cudaMemsetAsync(p_scnt,  0,    NPAIR * sizeof(int));
    cudaMemsetAsync(p_relnz, 0,    RR * sizeof(int));
    cudaMemsetAsync(p_fill,  0,    RR * sizeof(int));
    cudaMemsetAsync(p_bins,  0,    MAXBLK * sizeof(int));
    cudaMemsetAsync(p_vnode, 0xFF, NVROW * sizeof(int));
    cudaMemsetAsync(p_out,   0,    (size_t)NN * DD * sizeof(float));

    // ---- prep ----
    k_prep1<<<PREP1_GRID, T>>>(x_ids, emb, W1, root1, W2, root2, ei, et);
    k_inv_relnz<<<(NPAIR + T - 1) / T, T>>>();
    k_bases_blockrel<<<1, 1024>>>();
    k_compact<<<(NPAIR + T - 1) / T, T>>>();
    k_scan<<<1, 1024>>>();
    k_eperm<<<(EE + T - 1) / T, T>>>(ei, et);

    const int allBlocks = MAXBLK + ROOTBLK;   // rel blocks first, then root

    // ---- layer 1 ----
    k_gemm_all<<<allBlocks, 256, GSM_TOTAL>>>(0);
    k_act_relu<<<(NN * 32) / T, T>>>(b1);   // also zeroes g_out for layer 2

    // ---- layer 2 ----
    k_gemm_all<<<allBlocks, 256, GSM_TOTAL>>>(KT * DD);
    k_sigmoid<<<(NN * 32) / T, T>>>(b2, out);
}

// round 11
// speedup vs baseline: 1.5606x; 1.5606x over previous
#include <cuda_runtime.h>
#include <cuda_bf16.h>
#include <math.h>
#include <stdint.h>

// Problem constants
#define NN 100000      // nodes
#define EE 500000      // edges
#define RR 8           // relations
#define DD 128         // hidden
#define KT 1152        // Wt rows: R*D (relations) + D (root)
#define NPAIR (NN * RR)                     // 800000 (node, rel) pairs
#define TM 64                               // GEMM tile M
#define MAXBLK ((NPAIR + RR * (TM - 1) + TM - 1) / TM)   // max 64-row blocks after padding
#define NVROW (MAXBLK * TM)
#define ROOTBLK ((NN + TM - 1) / TM)        // 1563

// -------- scratch (device globals; no allocation allowed) --------
__device__ __nv_bfloat16 g_xhi[(size_t)NN * DD];
__device__ __nv_bfloat16 g_xlo[(size_t)NN * DD];
__device__ __nv_bfloat16 g_wthi[2 * (size_t)KT * DD];   // both layers
__device__ __nv_bfloat16 g_wtlo[2 * (size_t)KT * DD];
__device__ float g_out[(size_t)NN * DD];
__device__ float g_inv[NPAIR];       // 1/indeg(dst,rel)
__device__ int   g_cnt[NPAIR];       // in-degree per (dst,rel)
__device__ int   g_scnt[NPAIR];      // out-degree per (src,rel)
__device__ int   g_pos[NPAIR];       // (src,rel) -> virtual row
__device__ int   g_vnode[NVROW];     // virtual row -> node (-1 = pad)
__device__ int   g_relnz[RR];
__device__ int   g_fill[RR];
__device__ int   g_base[RR + 1];
__device__ int   g_nblk;             // active blocks
__device__ int   g_blockrel[MAXBLK];
__device__ int   g_bins[MAXBLK];
__device__ int   g_ptr[MAXBLK + 1];
__device__ int   g_cur[MAXBLK];
__device__ int   g_els[EE];          // sorted edges: local src row (pos % TM)
__device__ int   g_ed[EE];           // sorted edges: dst
__device__ float g_einv[EE];         // sorted edges: 1/cnt(dst,rel)

// ---------------- helpers ----------------
__device__ __forceinline__ uint32_t saddr(const void* p) {
    return (uint32_t)__cvta_generic_to_shared(p);
}
__device__ __forceinline__ void ldsm_x4(uint32_t* r, uint32_t addr) {
    asm volatile("ldmatrix.sync.aligned.m8n8.x4.shared.b16 {%0,%1,%2,%3}, [%4];"
                 : "=r"(r[0]), "=r"(r[1]), "=r"(r[2]), "=r"(r[3]) : "r"(addr));
}
__device__ __forceinline__ void mma_bf16(float* c, const uint32_t* a, const uint32_t* b) {
    asm volatile("mma.sync.aligned.m16n8k16.row.col.f32.bf16.bf16.f32 "
                 "{%0,%1,%2,%3}, {%4,%5,%6,%7}, {%8,%9}, {%0,%1,%2,%3};"
                 : "+f"(c[0]), "+f"(c[1]), "+f"(c[2]), "+f"(c[3])
                 : "r"(a[0]), "r"(a[1]), "r"(a[2]), "r"(a[3]), "r"(b[0]), "r"(b[1]));
}
__device__ __forceinline__ void split2(float v, __nv_bfloat16& h, __nv_bfloat16& l) {
    h = __float2bfloat16(v);
    l = __float2bfloat16(v - __bfloat162float(h));
}
__device__ __forceinline__ void red_add4(float* p, float4 v) {
    asm volatile("red.global.add.v4.f32 [%0], {%1, %2, %3, %4};"
                 :: "l"(p), "f"(v.x), "f"(v.y), "f"(v.z), "f"(v.w) : "memory");
}
__device__ __forceinline__ void red_add2(float* p, float2 v) {
    asm volatile("red.global.add.v2.f32 [%0], {%1, %2};"
                 :: "l"(p), "f"(v.x), "f"(v.y) : "memory");
}
// 16B async copy; src_size = 16 (copy) or 0 (zero-fill, pad rows)
__device__ __forceinline__ void cp16(uint32_t dst, const void* src, int src_size) {
    asm volatile("cp.async.cg.shared.global [%0], [%1], 16, %2;"
                 :: "r"(dst), "l"(src), "r"(src_size) : "memory");
}
__device__ __forceinline__ void cp_commit_wait() {
    asm volatile("cp.async.commit_group;" ::: "memory");
    asm volatile("cp.async.wait_group 0;" ::: "memory");
}

// ---------------- fused prep: gather_split | wsplit(L1) | wsplit(L2) | hist2 ----------------
#define P_GATHER (NN * 32 / 256)                 // 12500 blocks
#define P_WS     ((KT * DD) / 256)               // 576 blocks each
#define P_HIST   ((EE + 255) / 256)              // 1954 blocks
#define PREP1_GRID (P_GATHER + 2 * P_WS + P_HIST)

__global__ void k_prep1(const int* __restrict__ ids, const float* __restrict__ emb,
                        const float* __restrict__ W1, const float* __restrict__ root1,
                        const float* __restrict__ W2, const float* __restrict__ root2,
                        const int* __restrict__ ei, const int* __restrict__ et) {
    int b = blockIdx.x;
    if (b < P_GATHER) {
        int t = b * 256 + threadIdx.x;
        int n = t >> 5, l4 = (t & 31) * 4;
        if (n >= NN) return;
        float4 v = *((const float4*)(emb + (size_t)ids[n] * DD + l4));
        __nv_bfloat16 h0, h1, h2, h3, l0, l1, l2, l3;
        split2(v.x, h0, l0); split2(v.y, h1, l1); split2(v.z, h2, l2); split2(v.w, h3, l3);
        __nv_bfloat162* ph = (__nv_bfloat162*)(g_xhi + (size_t)n * DD + l4);
        __nv_bfloat162* pl = (__nv_bfloat162*)(g_xlo + (size_t)n * DD + l4);
        ph[0] = __nv_bfloat162{h0, h1}; ph[1] = __nv_bfloat162{h2, h3};
        pl[0] = __nv_bfloat162{l0, l1}; pl[1] = __nv_bfloat162{l2, l3};
        return;
    }
    b -= P_GATHER;
    if (b < 2 * P_WS) {
        int layer = b >= P_WS;
        int t = (b - layer * P_WS) * 256 + threadIdx.x;
        const float* W     = layer ? W2 : W1;
        const float* rootM = layer ? root2 : root1;
        int loff = layer * KT * DD;
        int c = t >> 7, d = t & 127;
        float v;
        if (c < RR * DD) {
            int r = c >> 7, f = c & 127;
            v = W[((size_t)r * DD + d) * DD + f];
        } else {
            v = rootM[(size_t)d * DD + (c - RR * DD)];
        }
        __nv_bfloat16 h, l; split2(v, h, l);
        g_wthi[loff + t] = h; g_wtlo[loff + t] = l;
        return;
    }
    b -= 2 * P_WS;
    {
        int e = b * 256 + threadIdx.x;
        if (e >= EE) return;
        int src = ei[e], dst = ei[EE + e], r = et[e];
        atomicAdd(&g_cnt[dst * RR + r], 1);
        atomicAdd(&g_scnt[src * RR + r], 1);
    }
}

// inv + per-relation live-pair counts (block-aggregated atomics)
__global__ void k_inv_relnz() {
    __shared__ int c[RR];
    if (threadIdx.x < RR) c[threadIdx.x] = 0;
    __syncthreads();
    int t = blockIdx.x * blockDim.x + threadIdx.x;
    if (t < NPAIR) {
        int n = g_cnt[t];
        g_inv[t] = n > 0 ? 1.0f / (float)n : 0.0f;
        if (g_scnt[t] > 0) atomicAdd(&c[t & (RR - 1)], 1);
    }
    __syncthreads();
    if (threadIdx.x < RR && c[threadIdx.x] > 0) atomicAdd(&g_relnz[threadIdx.x], c[threadIdx.x]);
}

// bases (serial, 8 iters) + blockrel fill, single block
__global__ void k_bases_blockrel() {
    __shared__ int sbase[RR + 1];
    if (threadIdx.x == 0) {
        int b = 0;
        g_base[0] = 0; sbase[0] = 0;
        for (int r = 0; r < RR; r++) {
            b += (g_relnz[r] + TM - 1) & ~(TM - 1);
            g_base[r + 1] = b; sbase[r + 1] = b;
        }
        g_nblk = b / TM;
    }
    __syncthreads();
    for (int i = threadIdx.x; i < MAXBLK; i += blockDim.x) {
        int row = i * TM, rel = 0;
        for (int r = 0; r < RR; r++)
            if (row >= sbase[r] && row < sbase[r + 1]) rel = r;
        g_blockrel[i] = rel;
    }
}

// compact live pairs into virtual rows + per-block edge bin counts.
// Block-aggregated g_fill atomics: smem rank within block, ONE global
// atomicAdd per (block, relation).
__global__ void k_compact() {
    __shared__ int cnt[RR];
    __shared__ int basep[RR];
    int t = blockIdx.x * 256 + threadIdx.x;
    if (threadIdx.x < RR) cnt[threadIdx.x] = 0;
    __syncthreads();
    int sc = 0, rel = 0, rank = 0, node = 0;
    bool live = false;
    if (t < NPAIR) {
        sc = g_scnt[t];
        if (sc > 0) {
            live = true;
            node = t >> 3;              // RR == 8
            rel  = t & 7;
            rank = atomicAdd(&cnt[rel], 1);
        }
    }
    __syncthreads();
    if (threadIdx.x < RR)
        basep[threadIdx.x] = cnt[threadIdx.x] ? atomicAdd(&g_fill[threadIdx.x], cnt[threadIdx.x]) : 0;
    __syncthreads();
    if (live) {
        int pos = g_base[rel] + basep[rel] + rank;
        g_vnode[pos] = node;
        g_pos[t] = pos;
        atomicAdd(&g_bins[pos / TM], sc);   // bin size = sum of out-degrees
    }
}

// single-block exclusive scan over MAXBLK bins
__global__ void k_scan() {
    __shared__ int wsum[32];
    const int tid = threadIdx.x;
    const int per = (MAXBLK + 1023) / 1024;
    int base = tid * per;
    int loc[16]; int s = 0;
    for (int i = 0; i < per; i++) {
        int idx = base + i;
        int v = (idx < MAXBLK) ? g_bins[idx] : 0;
        loc[i] = s; s += v;
    }
    int lane = tid & 31, wid = tid >> 5;
    int x = s;
    for (int d = 1; d < 32; d <<= 1) {
        int y = __shfl_up_sync(0xffffffffu, x, d);
        if (lane >= d) x += y;
    }
    if (lane == 31) wsum[wid] = x;
    __syncthreads();
    if (wid == 0) {
        int y = wsum[lane];
        for (int d = 1; d < 32; d <<= 1) {
            int z = __shfl_up_sync(0xffffffffu, y, d);
            if (lane >= d) y += z;
        }
        wsum[lane] = y;
    }
    __syncthreads();
    int excl = x - s + (wid > 0 ? wsum[wid - 1] : 0);
    for (int i = 0; i < per; i++) {
        int idx = base + i;
        if (idx < MAXBLK) { int p = excl + loc[i]; g_ptr[idx] = p; g_cur[idx] = p; }
    }
    if (tid == 1023) g_ptr[MAXBLK] = excl + s;
}

__global__ void k_eperm(const int* __restrict__ ei, const int* __restrict__ et) {
    int e = blockIdx.x * blockDim.x + threadIdx.x;
    if (e >= EE) return;
    int src = ei[e], dst = ei[EE + e], r = et[e];
    int pos = g_pos[src * RR + r];
    int i = atomicAdd(&g_cur[pos / TM], 1);
    g_els[i]  = pos % TM;
    g_ed[i]   = dst;
    g_einv[i] = g_inv[dst * RR + r];
}

// ---------------- combined GEMM (rel blocks first, then root blocks) ----------------
// g_out MUST be zeroed before this launch; BOTH paths accumulate via red.add.
#define PADK 136
#define GSM_AH 0
#define GSM_AL 17408
#define GSM_BH 34816
#define GSM_BL 69632
#define GSM_TOTAL 104448     // per-CTA dynamic smem; 2 CTAs/SM

// MMA core: 64(M) x 128(N) x 128(K), warps 2(M) x 4(N), warp tile 32x32
#define MMA_CORE(Ah, Al, Bh, Bl, acc)                                              \
    {                                                                              \
        _Pragma("unroll")                                                          \
        for (int ks = 0; ks < 8; ks++) {                                           \
            const int k0 = ks * 16;                                                \
            uint32_t ah[2][4], al[2][4];                                           \
            _Pragma("unroll")                                                      \
            for (int mf = 0; mf < 2; mf++) {                                       \
                ldsm_x4(ah[mf], saddr(Ah + (a_row + mf * 16) * PADK + k0 + a_koff));\
                ldsm_x4(al[mf], saddr(Al + (a_row + mf * 16) * PADK + k0 + a_koff));\
            }                                                                      \
            _Pragma("unroll")                                                      \
            for (int np = 0; np < 2; np++) {                                       \
                uint32_t bh[4], bl[4];                                             \
                ldsm_x4(bh, saddr(Bh + (b_nrow + np * 16) * PADK + k0 + b_koff));  \
                ldsm_x4(bl, saddr(Bl + (b_nrow + np * 16) * PADK + k0 + b_koff));  \
                _Pragma("unroll")                                                  \
                for (int sub = 0; sub < 2; sub++) {                                \
                    uint32_t bfh[2] = { bh[sub], bh[sub + 2] };                    \
                    uint32_t bfl[2] = { bl[sub], bl[sub + 2] };                    \
                    _Pragma("unroll")                                              \
                    for (int mf = 0; mf < 2; mf++) {                               \
                        float* c = acc[mf][np * 2 + sub];                          \
                        mma_bf16(c, ah[mf], bfh);                                  \
                        mma_bf16(c, ah[mf], bfl);                                  \
                        mma_bf16(c, al[mf], bfh);                                  \
                    }                                                              \
                }                                                                  \
            }                                                                      \
        }                                                                          \
    }

__global__ __launch_bounds__(256, 2)
void k_gemm_all(int loff) {
    extern __shared__ char sm[];
    __nv_bfloat16* Ah = (__nv_bfloat16*)(sm + GSM_AH);
    __nv_bfloat16* Al = (__nv_bfloat16*)(sm + GSM_AL);
    __nv_bfloat16* Bh = (__nv_bfloat16*)(sm + GSM_BH);
    __nv_bfloat16* Bl = (__nv_bfloat16*)(sm + GSM_BL);
    float*         hsm = (float*)(sm + GSM_BH);   // aliases B after MMA (rel path)

    const int tid  = threadIdx.x;
    const int lane = tid & 31, warp = tid >> 5;

    const bool isRel = (int)blockIdx.x < MAXBLK;
    if (isRel && (int)blockIdx.x >= g_nblk) return;

    const int brow = isRel ? g_blockrel[blockIdx.x] : RR;   // B row-block in Wt
    const int row0 = isRel ? (int)blockIdx.x * TM : ((int)blockIdx.x - MAXBLK) * TM;

    // ---- async load A (gathered rows; pads zero-fill via src_size=0) ----
    for (int v = tid; v < 1024; v += 256) {
        int r = v >> 4, c8 = (v & 15) << 3;
        int node;
        if (isRel) node = g_vnode[row0 + r];
        else       node = (row0 + r < NN) ? row0 + r : -1;
        int sz = node >= 0 ? 16 : 0;
        size_t gofs = (size_t)(node >= 0 ? node : 0) * DD + c8;
        cp16(saddr(Ah + r * PADK + c8), g_xhi + gofs, sz);
        cp16(saddr(Al + r * PADK + c8), g_xlo + gofs, sz);
    }
    // ---- async load B ----
    for (int v = tid; v < 2048; v += 256) {
        int r = v >> 4, c8 = (v & 15) << 3;
        const size_t gofs = (size_t)loff + (size_t)(brow * DD + r) * DD + c8;
        cp16(saddr(Bh + r * PADK + c8), g_wthi + gofs, 16);
        cp16(saddr(Bl + r * PADK + c8), g_wtlo + gofs, 16);
    }
    cp_commit_wait();
    __syncthreads();

    const int wm = warp & 1, wn = warp >> 1;
    const int a_row  = wm * 32 + (lane & 15);
    const int a_koff = (lane >> 4) * 8;
    const int b_nrow = wn * 32 + (lane & 7) + ((lane >> 3) & 1) * 8;
    const int b_koff = (lane >> 4) * 8;

    float acc[2][4][4];
#pragma unroll
    for (int i = 0; i < 2; i++)
#pragma unroll
        for (int j = 0; j < 4; j++)
#pragma unroll
            for (int k = 0; k < 4; k++) acc[i][j][k] = 0.f;

    MMA_CORE(Ah, Al, Bh, Bl, acc)

    if (!isRel) {
        // root path: accumulate into pre-zeroed g_out (race-free vs rel scatter)
#pragma unroll
        for (int mf = 0; mf < 2; mf++) {
#pragma unroll
            for (int nf = 0; nf < 4; nf++) {
                int r = row0 + wm * 32 + mf * 16 + (lane >> 2);
                int c = wn * 32 + nf * 8 + (lane & 3) * 2;
                float* cc = acc[mf][nf];
                if (r < NN)
                    red_add2(g_out + (size_t)r * DD + c, make_float2(cc[0], cc[1]));
                if (r + 8 < NN)
                    red_add2(g_out + (size_t)(r + 8) * DD + c, make_float2(cc[2], cc[3]));
            }
        }
        return;
    }

    __syncthreads();   // all warps done reading B before hsm overwrites it

    // h tile -> smem (aliased over B)
#pragma unroll
    for (int mf = 0; mf < 2; mf++) {
#pragma unroll
        for (int nf = 0; nf < 4; nf++) {
            int r = wm * 32 + mf * 16 + (lane >> 2);
            int c = wn * 32 + nf * 8 + (lane & 3) * 2;
            float* cc = acc[mf][nf];
            *(float2*)(hsm + r * 128 + c)       = make_float2(cc[0], cc[1]);
            *(float2*)(hsm + (r + 8) * 128 + c) = make_float2(cc[2], cc[3]);
        }
    }
    __syncthreads();

    // scatter this block's edges (one warp per edge)
    int s = g_ptr[blockIdx.x], e2 = g_ptr[blockIdx.x + 1];
    for (int i = s + warp; i < e2; i += 8) {
        int   ls  = g_els[i];
        int   dst = g_ed[i];
        float inv = g_einv[i];
        float4 v = *(const float4*)(hsm + ls * 128 + lane * 4);
        v.x *= inv; v.y *= inv; v.z *= inv; v.w *= inv;
        red_add4(g_out + (size_t)dst * DD + lane * 4, v);
    }
}

// ---------------- activations ----------------
// relu + split; ALSO zeroes g_out in the same pass (replaces the L2 memset)
__global__ void k_act_relu(const float* __restrict__ bias) {
    int t = blockIdx.x * blockDim.x + threadIdx.x;
    if (t >= NN * 32) return;
    float4 v = *(const float4*)(g_out + (size_t)t * 4);
    float4 b = __ldg((const float4*)(bias + (t & 31) * 4));
    v.x = fmaxf(v.x + b.x, 0.f); v.y = fmaxf(v.y + b.y, 0.f);
    v.z = fmaxf(v.z + b.z, 0.f); v.w = fmaxf(v.w + b.w, 0.f);
    *(float4*)(g_out + (size_t)t * 4) = make_float4(0.f, 0.f, 0.f, 0.f);
    __nv_bfloat16 h0, h1, h2, h3, l0, l1, l2, l3;
    split2(v.x, h0, l0); split2(v.y, h1, l1); split2(v.z, h2, l2); split2(v.w, h3, l3);
    __nv_bfloat162* ph = (__nv_bfloat162*)(g_xhi + (size_t)t * 4);
    __nv_bfloat162* pl = (__nv_bfloat162*)(g_xlo + (size_t)t * 4);
    ph[0] = __nv_bfloat162{h0, h1}; ph[1] = __nv_bfloat162{h2, h3};
    pl[0] = __nv_bfloat162{l0, l1}; pl[1] = __nv_bfloat162{l2, l3};
}

__global__ void k_sigmoid(const float* __restrict__ bias, float* __restrict__ outp) {
    int t = blockIdx.x * blockDim.x + threadIdx.x;
    if (t >= NN * 32) return;
    float4 v = *(const float4*)(g_out + (size_t)t * 4);
    float4 b = __ldg((const float4*)(bias + (t & 31) * 4));
    v.x = 1.0f / (1.0f + __expf(-(v.x + b.x)));
    v.y = 1.0f / (1.0f + __expf(-(v.y + b.y)));
    v.z = 1.0f / (1.0f + __expf(-(v.z + b.z)));
    v.w = 1.0f / (1.0f + __expf(-(v.w + b.w)));
    *(float4*)(outp + (size_t)t * 4) = v;
}

// ---------------- launch ----------------
extern "C" void kernel_launch(void* const* d_in, const int* in_sizes, int n_in,
                              void* d_out, int out_size) {
    const int*   x_ids = (const int*)  d_in[0];
    const int*   ei    = (const int*)  d_in[1];   // [2, E]: src row then dst row
    const int*   et    = (const int*)  d_in[2];
    const float* emb   = (const float*)d_in[3];
    const float* W1    = (const float*)d_in[4];
    const float* root1 = (const float*)d_in[5];
    const float* b1    = (const float*)d_in[6];
    const float* W2    = (const float*)d_in[7];
    const float* root2 = (const float*)d_in[8];
    const float* b2    = (const float*)d_in[9];
    float*       out   = (float*)d_out;
    (void)in_sizes; (void)n_in; (void)out_size;

    cudaFuncSetAttribute(k_gemm_all, cudaFuncAttributeMaxDynamicSharedMemorySize, GSM_TOTAL);

    void *p_cnt, *p_scnt, *p_relnz, *p_fill, *p_bins, *p_vnode, *p_out;
    cudaGetSymbolAddress(&p_cnt,   g_cnt);
    cudaGetSymbolAddress(&p_scnt,  g_scnt);
    cudaGetSymbolAddress(&p_relnz, g_relnz);
    cudaGetSymbolAddress(&p_fill,  g_fill);
    cudaGetSymbolAddress(&p_bins,  g_bins);
    cudaGetSymbolAddress(&p_vnode, g_vnode);
    cudaGetSymbolAddress(&p_out,   g_out);

    const int T = 256;

    // ---- zero/init (async memsets; g_vnode = 0xFF.. == -1) ----
    cudaMemsetAsync(p_cnt,   0,    NPAIR * sizeof(int));
    cudaMemsetAsync(p_scnt,  0,    NPAIR * sizeof(int));
    cudaMemsetAsync(p_relnz, 0,    RR * sizeof(int));
    cudaMemsetAsync(p_fill,  0,    RR * sizeof(int));
    cudaMemsetAsync(p_bins,  0,    MAXBLK * sizeof(int));
    cudaMemsetAsync(p_vnode, 0xFF, NVROW * sizeof(int));
    cudaMemsetAsync(p_out,   0,    (size_t)NN * DD * sizeof(float));

    // ---- prep ----
    k_prep1<<<PREP1_GRID, T>>>(x_ids, emb, W1, root1, W2, root2, ei, et);
    k_inv_relnz<<<(NPAIR + T - 1) / T, T>>>();
    k_bases_blockrel<<<1, 1024>>>();
    k_compact<<<(NPAIR + T - 1) / T, T>>>();
    k_scan<<<1, 1024>>>();
    k_eperm<<<(EE + T - 1) / T, T>>>(ei, et);

    const int allBlocks = MAXBLK + ROOTBLK;   // rel blocks first, then root

    // ---- layer 1 ----
    k_gemm_all<<<allBlocks, 256, GSM_TOTAL>>>(0);
    k_act_relu<<<(NN * 32) / T, T>>>(b1);   // also zeroes g_out for layer 2

    // ---- layer 2 ----
    k_gemm_all<<<allBlocks, 256, GSM_TOTAL>>>(KT * DD);
    k_sigmoid<<<(NN * 32) / T, T>>>(b2, out);
}

// round 12
// speedup vs baseline: 1.9728x; 1.2641x over previous
#include <cuda_runtime.h>
#include <cuda_fp16.h>
#include <cuda_bf16.h>
#include <math.h>
#include <stdint.h>

// Problem constants
#define NN 100000      // nodes
#define EE 500000      // edges
#define RR 8           // relations
#define DD 128         // hidden
#define KT 1152        // Wt rows: R*D (relations) + D (root)
#define NPAIR (NN * RR)                     // 800000 (node, rel) pairs
#define TM 64                               // GEMM tile M
#define MAXBLK ((NPAIR + RR * (TM - 1) + TM - 1) / TM)   // max 64-row blocks after padding
#define NVROW (MAXBLK * TM)
#define ROOTBLK ((NN + TM - 1) / TM)        // 1563

// -------- scratch (device globals; no allocation allowed) --------
__device__ __half g_xhi[(size_t)NN * DD];    // x hi (fp16)
__device__ __half g_xlo[(size_t)NN * DD];    // x lo (fp16 residual; x = hi+lo exact to 2^-22)
__device__ __half g_wthi[2 * (size_t)KT * DD];   // weights fp16-hi only, both layers
__device__ float g_out[(size_t)NN * DD];
__device__ float g_inv[NPAIR];       // 1/indeg(dst,rel)
__device__ int   g_cnt[NPAIR];       // in-degree per (dst,rel)
__device__ int   g_scnt[NPAIR];      // out-degree per (src,rel)
__device__ int   g_pos[NPAIR];       // (src,rel) -> virtual row
__device__ int   g_vnode[NVROW];     // virtual row -> node (-1 = pad)
__device__ int   g_relnz[RR];
__device__ int   g_fill[RR];
__device__ int   g_base[RR + 1];
__device__ int   g_nblk;             // active blocks
__device__ int   g_blockrel[MAXBLK];
__device__ int   g_bins[MAXBLK];
__device__ int   g_ptr[MAXBLK + 1];
__device__ int   g_cur[MAXBLK];
__device__ int   g_els[EE];          // sorted edges: local src row (pos % TM)
__device__ int   g_ed[EE];           // sorted edges: dst
__device__ float g_einv[EE];         // sorted edges: 1/cnt(dst,rel)

// ---------------- helpers ----------------
__device__ __forceinline__ uint32_t saddr(const void* p) {
    return (uint32_t)__cvta_generic_to_shared(p);
}
__device__ __forceinline__ void ldsm_x4(uint32_t* r, uint32_t addr) {
    asm volatile("ldmatrix.sync.aligned.m8n8.x4.shared.b16 {%0,%1,%2,%3}, [%4];"
                 : "=r"(r[0]), "=r"(r[1]), "=r"(r[2]), "=r"(r[3]) : "r"(addr));
}
__device__ __forceinline__ void mma_f16(float* c, const uint32_t* a, const uint32_t* b) {
    asm volatile("mma.sync.aligned.m16n8k16.row.col.f32.f16.f16.f32 "
                 "{%0,%1,%2,%3}, {%4,%5,%6,%7}, {%8,%9}, {%0,%1,%2,%3};"
                 : "+f"(c[0]), "+f"(c[1]), "+f"(c[2]), "+f"(c[3])
                 : "r"(a[0]), "r"(a[1]), "r"(a[2]), "r"(a[3]), "r"(b[0]), "r"(b[1]));
}
__device__ __forceinline__ void split2h(float v, __half& h, __half& l) {
    h = __float2half(v);
    l = __float2half(v - __half2float(h));
}
__device__ __forceinline__ void red_add4(float* p, float4 v) {
    asm volatile("red.global.add.v4.f32 [%0], {%1, %2, %3, %4};"
                 :: "l"(p), "f"(v.x), "f"(v.y), "f"(v.z), "f"(v.w) : "memory");
}
__device__ __forceinline__ void red_add2(float* p, float2 v) {
    asm volatile("red.global.add.v2.f32 [%0], {%1, %2};"
                 :: "l"(p), "f"(v.x), "f"(v.y) : "memory");
}
// 16B async copy; src_size = 16 (copy) or 0 (zero-fill, pad rows)
__device__ __forceinline__ void cp16(uint32_t dst, const void* src, int src_size) {
    asm volatile("cp.async.cg.shared.global [%0], [%1], 16, %2;"
                 :: "r"(dst), "l"(src), "r"(src_size) : "memory");
}
__device__ __forceinline__ void cp_commit_wait() {
    asm volatile("cp.async.commit_group;" ::: "memory");
    asm volatile("cp.async.wait_group 0;" ::: "memory");
}

// ---------------- fused prep: gather_split | wsplit(L1) | wsplit(L2) | hist2 ----------------
#define P_GATHER (NN * 32 / 256)                 // 12500 blocks
#define P_WS     ((KT * DD) / 256)               // 576 blocks each
#define P_HIST   ((EE + 255) / 256)              // 1954 blocks
#define PREP1_GRID (P_GATHER + 2 * P_WS + P_HIST)

__global__ void k_prep1(const int* __restrict__ ids, const float* __restrict__ emb,
                        const float* __restrict__ W1, const float* __restrict__ root1,
                        const float* __restrict__ W2, const float* __restrict__ root2,
                        const int* __restrict__ ei, const int* __restrict__ et) {
    int b = blockIdx.x;
    if (b < P_GATHER) {
        int t = b * 256 + threadIdx.x;
        int n = t >> 5, l4 = (t & 31) * 4;
        if (n >= NN) return;
        float4 v = *((const float4*)(emb + (size_t)ids[n] * DD + l4));
        __half h0, h1, h2, h3, l0, l1, l2, l3;
        split2h(v.x, h0, l0); split2h(v.y, h1, l1); split2h(v.z, h2, l2); split2h(v.w, h3, l3);
        __half2* ph = (__half2*)(g_xhi + (size_t)n * DD + l4);
        __half2* pl = (__half2*)(g_xlo + (size_t)n * DD + l4);
        ph[0] = __half2{h0, h1}; ph[1] = __half2{h2, h3};
        pl[0] = __half2{l0, l1}; pl[1] = __half2{l2, l3};
        return;
    }
    b -= P_GATHER;
    if (b < 2 * P_WS) {
        int layer = b >= P_WS;
        int t = (b - layer * P_WS) * 256 + threadIdx.x;
        const float* W     = layer ? W2 : W1;
        const float* rootM = layer ? root2 : root1;
        int loff = layer * KT * DD;
        int c = t >> 7, d = t & 127;
        float v;
        if (c < RR * DD) {
            int r = c >> 7, f = c & 127;
            v = W[((size_t)r * DD + d) * DD + f];
        } else {
            v = rootM[(size_t)d * DD + (c - RR * DD)];
        }
        g_wthi[loff + t] = __float2half(v);
        return;
    }
    b -= 2 * P_WS;
    {
        int e = b * 256 + threadIdx.x;
        if (e >= EE) return;
        int src = ei[e], dst = ei[EE + e], r = et[e];
        atomicAdd(&g_cnt[dst * RR + r], 1);
        atomicAdd(&g_scnt[src * RR + r], 1);
    }
}

// inv + per-relation live-pair counts (block-aggregated atomics)
__global__ void k_inv_relnz() {
    __shared__ int c[RR];
    if (threadIdx.x < RR) c[threadIdx.x] = 0;
    __syncthreads();
    int t = blockIdx.x * blockDim.x + threadIdx.x;
    if (t < NPAIR) {
        int n = g_cnt[t];
        g_inv[t] = n > 0 ? 1.0f / (float)n : 0.0f;
        if (g_scnt[t] > 0) atomicAdd(&c[t & (RR - 1)], 1);
    }
    __syncthreads();
    if (threadIdx.x < RR && c[threadIdx.x] > 0) atomicAdd(&g_relnz[threadIdx.x], c[threadIdx.x]);
}

// bases (serial, 8 iters) + blockrel fill, single block
__global__ void k_bases_blockrel() {
    __shared__ int sbase[RR + 1];
    if (threadIdx.x == 0) {
        int b = 0;
        g_base[0] = 0; sbase[0] = 0;
        for (int r = 0; r < RR; r++) {
            b += (g_relnz[r] + TM - 1) & ~(TM - 1);
            g_base[r + 1] = b; sbase[r + 1] = b;
        }
        g_nblk = b / TM;
    }
    __syncthreads();
    for (int i = threadIdx.x; i < MAXBLK; i += blockDim.x) {
        int row = i * TM, rel = 0;
        for (int r = 0; r < RR; r++)
            if (row >= sbase[r] && row < sbase[r + 1]) rel = r;
        g_blockrel[i] = rel;
    }
}

// compact live pairs into virtual rows + per-block edge bin counts.
// Block-aggregated g_fill atomics: smem rank within block, ONE global
// atomicAdd per (block, relation).
__global__ void k_compact() {
    __shared__ int cnt[RR];
    __shared__ int basep[RR];
    int t = blockIdx.x * 256 + threadIdx.x;
    if (threadIdx.x < RR) cnt[threadIdx.x] = 0;
    __syncthreads();
    int sc = 0, rel = 0, rank = 0, node = 0;
    bool live = false;
    if (t < NPAIR) {
        sc = g_scnt[t];
        if (sc > 0) {
            live = true;
            node = t >> 3;              // RR == 8
            rel  = t & 7;
            rank = atomicAdd(&cnt[rel], 1);
        }
    }
    __syncthreads();
    if (threadIdx.x < RR)
        basep[threadIdx.x] = cnt[threadIdx.x] ? atomicAdd(&g_fill[threadIdx.x], cnt[threadIdx.x]) : 0;
    __syncthreads();
    if (live) {
        int pos = g_base[rel] + basep[rel] + rank;
        g_vnode[pos] = node;
        g_pos[t] = pos;
        atomicAdd(&g_bins[pos / TM], sc);   // bin size = sum of out-degrees
    }
}

// single-block exclusive scan over MAXBLK bins
__global__ void k_scan() {
    __shared__ int wsum[32];
    const int tid = threadIdx.x;
    const int per = (MAXBLK + 1023) / 1024;
    int base = tid * per;
    int loc[16]; int s = 0;
    for (int i = 0; i < per; i++) {
        int idx = base + i;
        int v = (idx < MAXBLK) ? g_bins[idx] : 0;
        loc[i] = s; s += v;
    }
    int lane = tid & 31, wid = tid >> 5;
    int x = s;
    for (int d = 1; d < 32; d <<= 1) {
        int y = __shfl_up_sync(0xffffffffu, x, d);
        if (lane >= d) x += y;
    }
    if (lane == 31) wsum[wid] = x;
    __syncthreads();
    if (wid == 0) {
        int y = wsum[lane];
        for (int d = 1; d < 32; d <<= 1) {
            int z = __shfl_up_sync(0xffffffffu, y, d);
            if (lane >= d) y += z;
        }
        wsum[lane] = y;
    }
    __syncthreads();
    int excl = x - s + (wid > 0 ? wsum[wid - 1] : 0);
    for (int i = 0; i < per; i++) {
        int idx = base + i;
        if (idx < MAXBLK) { int p = excl + loc[i]; g_ptr[idx] = p; g_cur[idx] = p; }
    }
    if (tid == 1023) g_ptr[MAXBLK] = excl + s;
}

__global__ void k_eperm(const int* __restrict__ ei, const int* __restrict__ et) {
    int e = blockIdx.x * blockDim.x + threadIdx.x;
    if (e >= EE) return;
    int src = ei[e], dst = ei[EE + e], r = et[e];
    int pos = g_pos[src * RR + r];
    int i = atomicAdd(&g_cur[pos / TM], 1);
    g_els[i]  = pos % TM;
    g_ed[i]   = dst;
    g_einv[i] = g_inv[dst * RR + r];
}

// ---------------- combined GEMM (rel blocks first, then root blocks) ----------------
// g_out MUST be zeroed before this launch; BOTH paths accumulate via red.add.
// fp16 2-term split: h = xh@Wh + xl@Wh (= x@Wh; residual x@Wl ~ 2^-12 rel).
#define PADK 136
#define GSM_AH 0
#define GSM_AL 17408
#define GSM_BH 34816
#define GSM_TOTAL 69632      // per-CTA dynamic smem; 3 CTAs/SM

// MMA core: 64(M) x 128(N) x 128(K), warps 2(M) x 4(N), warp tile 32x32; 2 terms
#define MMA_CORE(Ah, Al, Bh, acc)                                                  \
    {                                                                              \
        _Pragma("unroll")                                                          \
        for (int ks = 0; ks < 8; ks++) {                                           \
            const int k0 = ks * 16;                                                \
            uint32_t ah[2][4], al[2][4];                                           \
            _Pragma("unroll")                                                      \
            for (int mf = 0; mf < 2; mf++) {                                       \
                ldsm_x4(ah[mf], saddr(Ah + (a_row + mf * 16) * PADK + k0 + a_koff));\
                ldsm_x4(al[mf], saddr(Al + (a_row + mf * 16) * PADK + k0 + a_koff));\
            }                                                                      \
            _Pragma("unroll")                                                      \
            for (int np = 0; np < 2; np++) {                                       \
                uint32_t bh[4];                                                    \
                ldsm_x4(bh, saddr(Bh + (b_nrow + np * 16) * PADK + k0 + b_koff));  \
                _Pragma("unroll")                                                  \
                for (int sub = 0; sub < 2; sub++) {                                \
                    uint32_t bfh[2] = { bh[sub], bh[sub + 2] };                    \
                    _Pragma("unroll")                                              \
                    for (int mf = 0; mf < 2; mf++) {                               \
                        float* c = acc[mf][np * 2 + sub];                          \
                        mma_f16(c, ah[mf], bfh);                                   \
                        mma_f16(c, al[mf], bfh);                                   \
                    }                                                              \
                }                                                                  \
            }                                                                      \
        }                                                                          \
    }

__global__ __launch_bounds__(256, 3)
void k_gemm_all(int loff) {
    extern __shared__ char sm[];
    __half* Ah = (__half*)(sm + GSM_AH);
    __half* Al = (__half*)(sm + GSM_AL);
    __half* Bh = (__half*)(sm + GSM_BH);
    float*  hsm = (float*)(sm + GSM_BH);   // aliases B after MMA (rel path; 32KB <= 34.8KB)

    const int tid  = threadIdx.x;
    const int lane = tid & 31, warp = tid >> 5;

    const bool isRel = (int)blockIdx.x < MAXBLK;
    if (isRel && (int)blockIdx.x >= g_nblk) return;

    const int brow = isRel ? g_blockrel[blockIdx.x] : RR;   // B row-block in Wt
    const int row0 = isRel ? (int)blockIdx.x * TM : ((int)blockIdx.x - MAXBLK) * TM;

    // ---- async load A (gathered rows; pads zero-fill via src_size=0) ----
    for (int v = tid; v < 1024; v += 256) {
        int r = v >> 4, c8 = (v & 15) << 3;
        int node;
        if (isRel) node = g_vnode[row0 + r];
        else       node = (row0 + r < NN) ? row0 + r : -1;
        int sz = node >= 0 ? 16 : 0;
        size_t gofs = (size_t)(node >= 0 ? node : 0) * DD + c8;
        cp16(saddr(Ah + r * PADK + c8), g_xhi + gofs, sz);
        cp16(saddr(Al + r * PADK + c8), g_xlo + gofs, sz);
    }
    // ---- async load B (hi only) ----
    for (int v = tid; v < 2048; v += 256) {
        int r = v >> 4, c8 = (v & 15) << 3;
        const size_t gofs = (size_t)loff + (size_t)(brow * DD + r) * DD + c8;
        cp16(saddr(Bh + r * PADK + c8), g_wthi + gofs, 16);
    }
    cp_commit_wait();
    __syncthreads();

    const int wm = warp & 1, wn = warp >> 1;
    const int a_row  = wm * 32 + (lane & 15);
    const int a_koff = (lane >> 4) * 8;
    const int b_nrow = wn * 32 + (lane & 7) + ((lane >> 3) & 1) * 8;
    const int b_koff = (lane >> 4) * 8;

    float acc[2][4][4];
#pragma unroll
    for (int i = 0; i < 2; i++)
#pragma unroll
        for (int j = 0; j < 4; j++)
#pragma unroll
            for (int k = 0; k < 4; k++) acc[i][j][k] = 0.f;

    MMA_CORE(Ah, Al, Bh, acc)

    if (!isRel) {
        // root path: accumulate into pre-zeroed g_out (race-free vs rel scatter)
#pragma unroll
        for (int mf = 0; mf < 2; mf++) {
#pragma unroll
            for (int nf = 0; nf < 4; nf++) {
                int r = row0 + wm * 32 + mf * 16 + (lane >> 2);
                int c = wn * 32 + nf * 8 + (lane & 3) * 2;
                float* cc = acc[mf][nf];
                if (r < NN)
                    red_add2(g_out + (size_t)r * DD + c, make_float2(cc[0], cc[1]));
                if (r + 8 < NN)
                    red_add2(g_out + (size_t)(r + 8) * DD + c, make_float2(cc[2], cc[3]));
            }
        }
        return;
    }

    __syncthreads();   // all warps done reading B before hsm overwrites it

    // h tile -> smem (aliased over B)
#pragma unroll
    for (int mf = 0; mf < 2; mf++) {
#pragma unroll
        for (int nf = 0; nf < 4; nf++) {
            int r = wm * 32 + mf * 16 + (lane >> 2);
            int c = wn * 32 + nf * 8 + (lane & 3) * 2;
            float* cc = acc[mf][nf];
            *(float2*)(hsm + r * 128 + c)       = make_float2(cc[0], cc[1]);
            *(float2*)(hsm + (r + 8) * 128 + c) = make_float2(cc[2], cc[3]);
        }
    }
    __syncthreads();

    // scatter this block's edges (one warp per edge)
    int s = g_ptr[blockIdx.x], e2 = g_ptr[blockIdx.x + 1];
    for (int i = s + warp; i < e2; i += 8) {
        int   ls  = g_els[i];
        int   dst = g_ed[i];
        float inv = g_einv[i];
        float4 v = *(const float4*)(hsm + ls * 128 + lane * 4);
        v.x *= inv; v.y *= inv; v.z *= inv; v.w *= inv;
        red_add4(g_out + (size_t)dst * DD + lane * 4, v);
    }
}

// ---------------- activations ----------------
// relu + split; ALSO zeroes g_out in the same pass (replaces the L2 memset)
__global__ void k_act_relu(const float* __restrict__ bias) {
    int t = blockIdx.x * blockDim.x + threadIdx.x;
    if (t >= NN * 32) return;
    float4 v = *(const float4*)(g_out + (size_t)t * 4);
    float4 b = __ldg((const float4*)(bias + (t & 31) * 4));
    v.x = fmaxf(v.x + b.x, 0.f); v.y = fmaxf(v.y + b.y, 0.f);
    v.z = fmaxf(v.z + b.z, 0.f); v.w = fmaxf(v.w + b.w, 0.f);
    *(float4*)(g_out + (size_t)t * 4) = make_float4(0.f, 0.f, 0.f, 0.f);
    __half h0, h1, h2, h3, l0, l1, l2, l3;
    split2h(v.x, h0, l0); split2h(v.y, h1, l1); split2h(v.z, h2, l2); split2h(v.w, h3, l3);
    __half2* ph = (__half2*)(g_xhi + (size_t)t * 4);
    __half2* pl = (__half2*)(g_xlo + (size_t)t * 4);
    ph[0] = __half2{h0, h1}; ph[1] = __half2{h2, h3};
    pl[0] = __half2{l0, l1}; pl[1] = __half2{l2, l3};
}

__global__ void k_sigmoid(const float* __restrict__ bias, float* __restrict__ outp) {
    int t = blockIdx.x * blockDim.x + threadIdx.x;
    if (t >= NN * 32) return;
    float4 v = *(const float4*)(g_out + (size_t)t * 4);
    float4 b = __ldg((const float4*)(bias + (t & 31) * 4));
    v.x = 1.0f / (1.0f + __expf(-(v.x + b.x)));
    v.y = 1.0f / (1.0f + __expf(-(v.y + b.y)));
    v.z = 1.0f / (1.0f + __expf(-(v.z + b.z)));
    v.w = 1.0f / (1.0f + __expf(-(v.w + b.w)));
    *(float4*)(outp + (size_t)t * 4) = v;
}

// ---------------- launch ----------------
extern "C" void kernel_launch(void* const* d_in, const int* in_sizes, int n_in,
                              void* d_out, int out_size) {
    const int*   x_ids = (const int*)  d_in[0];
    const int*   ei    = (const int*)  d_in[1];   // [2, E]: src row then dst row
    const int*   et    = (const int*)  d_in[2];
    const float* emb   = (const float*)d_in[3];
    const float* W1    = (const float*)d_in[4];
    const float* root1 = (const float*)d_in[5];
    const float* b1    = (const float*)d_in[6];
    const float* W2    = (const float*)d_in[7];
    const float* root2 = (const float*)d_in[8];
    const float* b2    = (const float*)d_in[9];
    float*       out   = (float*)d_out;
    (void)in_sizes; (void)n_in; (void)out_size;

    cudaFuncSetAttribute(k_gemm_all, cudaFuncAttributeMaxDynamicSharedMemorySize, GSM_TOTAL);

    void *p_cnt, *p_scnt, *p_relnz, *p_fill, *p_bins, *p_vnode, *p_out;
    cudaGetSymbolAddress(&p_cnt,   g_cnt);
    cudaGetSymbolAddress(&p_scnt,  g_scnt);
    cudaGetSymbolAddress(&p_relnz, g_relnz);
    cudaGetSymbolAddress(&p_fill,  g_fill);
    cudaGetSymbolAddress(&p_bins,  g_bins);
    cudaGetSymbolAddress(&p_vnode, g_vnode);
    cudaGetSymbolAddress(&p_out,   g_out);

    const int T = 256;

    // ---- zero/init (async memsets; g_vnode = 0xFF.. == -1) ----
    cudaMemsetAsync(p_cnt,   0,    NPAIR * sizeof(int));
    cudaMemsetAsync(p_scnt,  0,    NPAIR * sizeof(int));
    cudaMemsetAsync(p_relnz, 0,    RR * sizeof(int));
    cudaMemsetAsync(p_fill,  0,    RR * sizeof(int));
    cudaMemsetAsync(p_bins,  0,    MAXBLK * sizeof(int));
    cudaMemsetAsync(p_vnode, 0xFF, NVROW * sizeof(int));
    cudaMemsetAsync(p_out,   0,    (size_t)NN * DD * sizeof(float));

    // ---- prep ----
    k_prep1<<<PREP1_GRID, T>>>(x_ids, emb, W1, root1, W2, root2, ei, et);
    k_inv_relnz<<<(NPAIR + T - 1) / T, T>>>();
    k_bases_blockrel<<<1, 1024>>>();
    k_compact<<<(NPAIR + T - 1) / T, T>>>();
    k_scan<<<1, 1024>>>();
    k_eperm<<<(EE + T - 1) / T, T>>>(ei, et);

    const int allBlocks = MAXBLK + ROOTBLK;   // rel blocks first, then root

    // ---- layer 1 ----
    k_gemm_all<<<allBlocks, 256, GSM_TOTAL>>>(0);
    k_act_relu<<<(NN * 32) / T, T>>>(b1);   // also zeroes g_out for layer 2

    // ---- layer 2 ----
    k_gemm_all<<<allBlocks, 256, GSM_TOTAL>>>(KT * DD);
    k_sigmoid<<<(NN * 32) / T, T>>>(b2, out);
}

// round 13
// speedup vs baseline: 2.4998x; 1.2671x over previous
#include <cuda_runtime.h>
#include <cuda_fp16.h>
#include <math.h>
#include <stdint.h>

// Problem constants
#define NN 100000      // nodes
#define EE 500000      // edges
#define RR 8           // relations
#define DD 128         // hidden
#define KT 1152        // Wt rows: R*D (relations) + D (root)
#define NPAIR (NN * RR)                     // 800000 (node, rel) pairs
#define TM 64                               // GEMM tile M
#define MAXBLK ((NPAIR + RR * (TM - 1) + TM - 1) / TM)   // max 64-row blocks after padding
#define NVROW (MAXBLK * TM)
#define ROOTBLK ((NN + TM - 1) / TM)        // 1563

// -------- scratch (device globals; no allocation allowed) --------
__device__ __half g_xh [(size_t)NN * DD];        // x (fp16)
__device__ __half g_wth[2 * (size_t)KT * DD];    // weights fp16, both layers
__device__ float g_out[(size_t)NN * DD];
__device__ float g_inv[NPAIR];       // 1/indeg(dst,rel)
__device__ int   g_cnt[NPAIR];       // in-degree per (dst,rel)
__device__ int   g_scnt[NPAIR];      // out-degree per (src,rel)
__device__ int   g_pos[NPAIR];       // (src,rel) -> virtual row
__device__ int   g_vnode[NVROW];     // virtual row -> node (-1 = pad)
__device__ int   g_relnz[RR];
__device__ int   g_fill[RR];
__device__ int   g_base[RR + 1];
__device__ int   g_nblk;             // active blocks
__device__ int   g_blockrel[MAXBLK];
__device__ int   g_bins[MAXBLK];
__device__ int   g_ptr[MAXBLK + 1];
__device__ int   g_cur[MAXBLK];
__device__ int   g_els[EE];          // sorted edges: local src row (pos % TM)
__device__ int   g_ed[EE];           // sorted edges: dst
__device__ float g_einv[EE];         // sorted edges: 1/cnt(dst,rel)

// ---------------- helpers ----------------
__device__ __forceinline__ uint32_t saddr(const void* p) {
    return (uint32_t)__cvta_generic_to_shared(p);
}
__device__ __forceinline__ void ldsm_x4(uint32_t* r, uint32_t addr) {
    asm volatile("ldmatrix.sync.aligned.m8n8.x4.shared.b16 {%0,%1,%2,%3}, [%4];"
                 : "=r"(r[0]), "=r"(r[1]), "=r"(r[2]), "=r"(r[3]) : "r"(addr));
}
__device__ __forceinline__ void mma_f16(float* c, const uint32_t* a, const uint32_t* b) {
    asm volatile("mma.sync.aligned.m16n8k16.row.col.f32.f16.f16.f32 "
                 "{%0,%1,%2,%3}, {%4,%5,%6,%7}, {%8,%9}, {%0,%1,%2,%3};"
                 : "+f"(c[0]), "+f"(c[1]), "+f"(c[2]), "+f"(c[3])
                 : "r"(a[0]), "r"(a[1]), "r"(a[2]), "r"(a[3]), "r"(b[0]), "r"(b[1]));
}
__device__ __forceinline__ void red_add4(float* p, float4 v) {
    asm volatile("red.global.add.v4.f32 [%0], {%1, %2, %3, %4};"
                 :: "l"(p), "f"(v.x), "f"(v.y), "f"(v.z), "f"(v.w) : "memory");
}
__device__ __forceinline__ void red_add2(float* p, float2 v) {
    asm volatile("red.global.add.v2.f32 [%0], {%1, %2};"
                 :: "l"(p), "f"(v.x), "f"(v.y) : "memory");
}
// 16B async copy; src_size = 16 (copy) or 0 (zero-fill, pad rows)
__device__ __forceinline__ void cp16(uint32_t dst, const void* src, int src_size) {
    asm volatile("cp.async.cg.shared.global [%0], [%1], 16, %2;"
                 :: "r"(dst), "l"(src), "r"(src_size) : "memory");
}
__device__ __forceinline__ void cp_commit_wait() {
    asm volatile("cp.async.commit_group;" ::: "memory");
    asm volatile("cp.async.wait_group 0;" ::: "memory");
}

// ---------------- fused prep: gather | wsplit(L1) | wsplit(L2) | hist2 ----------------
#define P_GATHER (NN * 32 / 256)                 // 12500 blocks
#define P_WS     ((KT * DD) / 256)               // 576 blocks each
#define P_HIST   ((EE + 255) / 256)              // 1954 blocks
#define PREP1_GRID (P_GATHER + 2 * P_WS + P_HIST)

__global__ void k_prep1(const int* __restrict__ ids, const float* __restrict__ emb,
                        const float* __restrict__ W1, const float* __restrict__ root1,
                        const float* __restrict__ W2, const float* __restrict__ root2,
                        const int* __restrict__ ei, const int* __restrict__ et) {
    int b = blockIdx.x;
    if (b < P_GATHER) {
        int t = b * 256 + threadIdx.x;
        int n = t >> 5, l4 = (t & 31) * 4;
        if (n >= NN) return;
        float4 v = *((const float4*)(emb + (size_t)ids[n] * DD + l4));
        __half2* ph = (__half2*)(g_xh + (size_t)n * DD + l4);
        ph[0] = __half2{__float2half(v.x), __float2half(v.y)};
        ph[1] = __half2{__float2half(v.z), __float2half(v.w)};
        return;
    }
    b -= P_GATHER;
    if (b < 2 * P_WS) {
        int layer = b >= P_WS;
        int t = (b - layer * P_WS) * 256 + threadIdx.x;
        const float* W     = layer ? W2 : W1;
        const float* rootM = layer ? root2 : root1;
        int loff = layer * KT * DD;
        int c = t >> 7, d = t & 127;
        float v;
        if (c < RR * DD) {
            int r = c >> 7, f = c & 127;
            v = W[((size_t)r * DD + d) * DD + f];
        } else {
            v = rootM[(size_t)d * DD + (c - RR * DD)];
        }
        g_wth[loff + t] = __float2half(v);
        return;
    }
    b -= 2 * P_WS;
    {
        int e = b * 256 + threadIdx.x;
        if (e >= EE) return;
        int src = ei[e], dst = ei[EE + e], r = et[e];
        atomicAdd(&g_cnt[dst * RR + r], 1);
        atomicAdd(&g_scnt[src * RR + r], 1);
    }
}

// inv + per-relation live-pair counts (block-aggregated atomics)
__global__ void k_inv_relnz() {
    __shared__ int c[RR];
    if (threadIdx.x < RR) c[threadIdx.x] = 0;
    __syncthreads();
    int t = blockIdx.x * blockDim.x + threadIdx.x;
    if (t < NPAIR) {
        int n = g_cnt[t];
        g_inv[t] = n > 0 ? 1.0f / (float)n : 0.0f;
        if (g_scnt[t] > 0) atomicAdd(&c[t & (RR - 1)], 1);
    }
    __syncthreads();
    if (threadIdx.x < RR && c[threadIdx.x] > 0) atomicAdd(&g_relnz[threadIdx.x], c[threadIdx.x]);
}

// bases (serial, 8 iters) + blockrel fill, single block
__global__ void k_bases_blockrel() {
    __shared__ int sbase[RR + 1];
    if (threadIdx.x == 0) {
        int b = 0;
        g_base[0] = 0; sbase[0] = 0;
        for (int r = 0; r < RR; r++) {
            b += (g_relnz[r] + TM - 1) & ~(TM - 1);
            g_base[r + 1] = b; sbase[r + 1] = b;
        }
        g_nblk = b / TM;
    }
    __syncthreads();
    for (int i = threadIdx.x; i < MAXBLK; i += blockDim.x) {
        int row = i * TM, rel = 0;
        for (int r = 0; r < RR; r++)
            if (row >= sbase[r] && row < sbase[r + 1]) rel = r;
        g_blockrel[i] = rel;
    }
}

// compact live pairs into virtual rows + per-block edge bin counts.
// Block-aggregated g_fill atomics: smem rank within block, ONE global
// atomicAdd per (block, relation).
__global__ void k_compact() {
    __shared__ int cnt[RR];
    __shared__ int basep[RR];
    int t = blockIdx.x * 256 + threadIdx.x;
    if (threadIdx.x < RR) cnt[threadIdx.x] = 0;
    __syncthreads();
    int sc = 0, rel = 0, rank = 0, node = 0;
    bool live = false;
    if (t < NPAIR) {
        sc = g_scnt[t];
        if (sc > 0) {
            live = true;
            node = t >> 3;              // RR == 8
            rel  = t & 7;
            rank = atomicAdd(&cnt[rel], 1);
        }
    }
    __syncthreads();
    if (threadIdx.x < RR)
        basep[threadIdx.x] = cnt[threadIdx.x] ? atomicAdd(&g_fill[threadIdx.x], cnt[threadIdx.x]) : 0;
    __syncthreads();
    if (live) {
        int pos = g_base[rel] + basep[rel] + rank;
        g_vnode[pos] = node;
        g_pos[t] = pos;
        atomicAdd(&g_bins[pos / TM], sc);   // bin size = sum of out-degrees
    }
}

// single-block exclusive scan over MAXBLK bins
__global__ void k_scan() {
    __shared__ int wsum[32];
    const int tid = threadIdx.x;
    const int per = (MAXBLK + 1023) / 1024;
    int base = tid * per;
    int loc[16]; int s = 0;
    for (int i = 0; i < per; i++) {
        int idx = base + i;
        int v = (idx < MAXBLK) ? g_bins[idx] : 0;
        loc[i] = s; s += v;
    }
    int lane = tid & 31, wid = tid >> 5;
    int x = s;
    for (int d = 1; d < 32; d <<= 1) {
        int y = __shfl_up_sync(0xffffffffu, x, d);
        if (lane >= d) x += y;
    }
    if (lane == 31) wsum[wid] = x;
    __syncthreads();
    if (wid == 0) {
        int y = wsum[lane];
        for (int d = 1; d < 32; d <<= 1) {
            int z = __shfl_up_sync(0xffffffffu, y, d);
            if (lane >= d) y += z;
        }
        wsum[lane] = y;
    }
    __syncthreads();
    int excl = x - s + (wid > 0 ? wsum[wid - 1] : 0);
    for (int i = 0; i < per; i++) {
        int idx = base + i;
        if (idx < MAXBLK) { int p = excl + loc[i]; g_ptr[idx] = p; g_cur[idx] = p; }
    }
    if (tid == 1023) g_ptr[MAXBLK] = excl + s;
}

__global__ void k_eperm(const int* __restrict__ ei, const int* __restrict__ et) {
    int e = blockIdx.x * blockDim.x + threadIdx.x;
    if (e >= EE) return;
    int src = ei[e], dst = ei[EE + e], r = et[e];
    int pos = g_pos[src * RR + r];
    int i = atomicAdd(&g_cur[pos / TM], 1);
    g_els[i]  = pos % TM;
    g_ed[i]   = dst;
    g_einv[i] = g_inv[dst * RR + r];
}

// ---------------- combined GEMM (rel blocks first, then root blocks) ----------------
// g_out MUST be zeroed before this launch; BOTH paths accumulate via red.add.
// Pure fp16: h = x_f16 @ W_f16 (fp32 accum).
#define PADK 136
#define GSM_A  0
#define GSM_B  17408
#define GSM_TOTAL 52224      // per-CTA dynamic smem; 4 CTAs/SM

// MMA core: 64(M) x 128(N) x 128(K), warps 2(M) x 4(N), warp tile 32x32; 1 term
#define MMA_CORE(As, Bs, acc)                                                      \
    {                                                                              \
        _Pragma("unroll")                                                          \
        for (int ks = 0; ks < 8; ks++) {                                           \
            const int k0 = ks * 16;                                                \
            uint32_t ah[2][4];                                                     \
            _Pragma("unroll")                                                      \
            for (int mf = 0; mf < 2; mf++)                                         \
                ldsm_x4(ah[mf], saddr(As + (a_row + mf * 16) * PADK + k0 + a_koff));\
            _Pragma("unroll")                                                      \
            for (int np = 0; np < 2; np++) {                                       \
                uint32_t bh[4];                                                    \
                ldsm_x4(bh, saddr(Bs + (b_nrow + np * 16) * PADK + k0 + b_koff));  \
                _Pragma("unroll")                                                  \
                for (int sub = 0; sub < 2; sub++) {                                \
                    uint32_t bfh[2] = { bh[sub], bh[sub + 2] };                    \
                    _Pragma("unroll")                                              \
                    for (int mf = 0; mf < 2; mf++)                                 \
                        mma_f16(acc[mf][np * 2 + sub], ah[mf], bfh);               \
                }                                                                  \
            }                                                                      \
        }                                                                          \
    }

__global__ __launch_bounds__(256, 4)
void k_gemm_all(int loff) {
    extern __shared__ char sm[];
    __half* As = (__half*)(sm + GSM_A);
    __half* Bs = (__half*)(sm + GSM_B);
    float*  hsm = (float*)(sm + GSM_B);   // aliases B after MMA (rel path; 32KB <= 34.8KB)

    const int tid  = threadIdx.x;
    const int lane = tid & 31, warp = tid >> 5;

    const bool isRel = (int)blockIdx.x < MAXBLK;
    if (isRel && (int)blockIdx.x >= g_nblk) return;

    const int brow = isRel ? g_blockrel[blockIdx.x] : RR;   // B row-block in Wt
    const int row0 = isRel ? (int)blockIdx.x * TM : ((int)blockIdx.x - MAXBLK) * TM;

    // ---- async load A (gathered rows; pads zero-fill via src_size=0) ----
    for (int v = tid; v < 1024; v += 256) {
        int r = v >> 4, c8 = (v & 15) << 3;
        int node;
        if (isRel) node = g_vnode[row0 + r];
        else       node = (row0 + r < NN) ? row0 + r : -1;
        int sz = node >= 0 ? 16 : 0;
        size_t gofs = (size_t)(node >= 0 ? node : 0) * DD + c8;
        cp16(saddr(As + r * PADK + c8), g_xh + gofs, sz);
    }
    // ---- async load B ----
    for (int v = tid; v < 2048; v += 256) {
        int r = v >> 4, c8 = (v & 15) << 3;
        const size_t gofs = (size_t)loff + (size_t)(brow * DD + r) * DD + c8;
        cp16(saddr(Bs + r * PADK + c8), g_wth + gofs, 16);
    }
    cp_commit_wait();
    __syncthreads();

    const int wm = warp & 1, wn = warp >> 1;
    const int a_row  = wm * 32 + (lane & 15);
    const int a_koff = (lane >> 4) * 8;
    const int b_nrow = wn * 32 + (lane & 7) + ((lane >> 3) & 1) * 8;
    const int b_koff = (lane >> 4) * 8;

    float acc[2][4][4];
#pragma unroll
    for (int i = 0; i < 2; i++)
#pragma unroll
        for (int j = 0; j < 4; j++)
#pragma unroll
            for (int k = 0; k < 4; k++) acc[i][j][k] = 0.f;

    MMA_CORE(As, Bs, acc)

    if (!isRel) {
        // root path: accumulate into pre-zeroed g_out (race-free vs rel scatter)
#pragma unroll
        for (int mf = 0; mf < 2; mf++) {
#pragma unroll
            for (int nf = 0; nf < 4; nf++) {
                int r = row0 + wm * 32 + mf * 16 + (lane >> 2);
                int c = wn * 32 + nf * 8 + (lane & 3) * 2;
                float* cc = acc[mf][nf];
                if (r < NN)
                    red_add2(g_out + (size_t)r * DD + c, make_float2(cc[0], cc[1]));
                if (r + 8 < NN)
                    red_add2(g_out + (size_t)(r + 8) * DD + c, make_float2(cc[2], cc[3]));
            }
        }
        return;
    }

    __syncthreads();   // all warps done reading B before hsm overwrites it

    // h tile -> smem (aliased over B)
#pragma unroll
    for (int mf = 0; mf < 2; mf++) {
#pragma unroll
        for (int nf = 0; nf < 4; nf++) {
            int r = wm * 32 + mf * 16 + (lane >> 2);
            int c = wn * 32 + nf * 8 + (lane & 3) * 2;
            float* cc = acc[mf][nf];
            *(float2*)(hsm + r * 128 + c)       = make_float2(cc[0], cc[1]);
            *(float2*)(hsm + (r + 8) * 128 + c) = make_float2(cc[2], cc[3]);
        }
    }
    __syncthreads();

    // scatter this block's edges (one warp per edge)
    int s = g_ptr[blockIdx.x], e2 = g_ptr[blockIdx.x + 1];
    for (int i = s + warp; i < e2; i += 8) {
        int   ls  = g_els[i];
        int   dst = g_ed[i];
        float inv = g_einv[i];
        float4 v = *(const float4*)(hsm + ls * 128 + lane * 4);
        v.x *= inv; v.y *= inv; v.z *= inv; v.w *= inv;
        red_add4(g_out + (size_t)dst * DD + lane * 4, v);
    }
}

// ---------------- activations ----------------
// relu + fp16 convert; ALSO zeroes g_out in the same pass (replaces the L2 memset)
__global__ void k_act_relu(const float* __restrict__ bias) {
    int t = blockIdx.x * blockDim.x + threadIdx.x;
    if (t >= NN * 32) return;
    float4 v = *(const float4*)(g_out + (size_t)t * 4);
    float4 b = __ldg((const float4*)(bias + (t & 31) * 4));
    v.x = fmaxf(v.x + b.x, 0.f); v.y = fmaxf(v.y + b.y, 0.f);
    v.z = fmaxf(v.z + b.z, 0.f); v.w = fmaxf(v.w + b.w, 0.f);
    *(float4*)(g_out + (size_t)t * 4) = make_float4(0.f, 0.f, 0.f, 0.f);
    __half2* ph = (__half2*)(g_xh + (size_t)t * 4);
    ph[0] = __half2{__float2half(v.x), __float2half(v.y)};
    ph[1] = __half2{__float2half(v.z), __float2half(v.w)};
}

__global__ void k_sigmoid(const float* __restrict__ bias, float* __restrict__ outp) {
    int t = blockIdx.x * blockDim.x + threadIdx.x;
    if (t >= NN * 32) return;
    float4 v = *(const float4*)(g_out + (size_t)t * 4);
    float4 b = __ldg((const float4*)(bias + (t & 31) * 4));
    v.x = 1.0f / (1.0f + __expf(-(v.x + b.x)));
    v.y = 1.0f / (1.0f + __expf(-(v.y + b.y)));
    v.z = 1.0f / (1.0f + __expf(-(v.z + b.z)));
    v.w = 1.0f / (1.0f + __expf(-(v.w + b.w)));
    *(float4*)(outp + (size_t)t * 4) = v;
}

// ---------------- launch ----------------
extern "C" void kernel_launch(void* const* d_in, const int* in_sizes, int n_in,
                              void* d_out, int out_size) {
    const int*   x_ids = (const int*)  d_in[0];
    const int*   ei    = (const int*)  d_in[1];   // [2, E]: src row then dst row
    const int*   et    = (const int*)  d_in[2];
    const float* emb   = (const float*)d_in[3];
    const float* W1    = (const float*)d_in[4];
    const float* root1 = (const float*)d_in[5];
    const float* b1    = (const float*)d_in[6];
    const float* W2    = (const float*)d_in[7];
    const float* root2 = (const float*)d_in[8];
    const float* b2    = (const float*)d_in[9];
    float*       out   = (float*)d_out;
    (void)in_sizes; (void)n_in; (void)out_size;

    cudaFuncSetAttribute(k_gemm_all, cudaFuncAttributeMaxDynamicSharedMemorySize, GSM_TOTAL);

    void *p_cnt, *p_scnt, *p_relnz, *p_fill, *p_bins, *p_vnode, *p_out;
    cudaGetSymbolAddress(&p_cnt,   g_cnt);
    cudaGetSymbolAddress(&p_scnt,  g_scnt);
    cudaGetSymbolAddress(&p_relnz, g_relnz);
    cudaGetSymbolAddress(&p_fill,  g_fill);
    cudaGetSymbolAddress(&p_bins,  g_bins);
    cudaGetSymbolAddress(&p_vnode, g_vnode);
    cudaGetSymbolAddress(&p_out,   g_out);

    const int T = 256;

    // ---- zero/init (async memsets; g_vnode = 0xFF.. == -1) ----
    cudaMemsetAsync(p_cnt,   0,    NPAIR * sizeof(int));
    cudaMemsetAsync(p_scnt,  0,    NPAIR * sizeof(int));
    cudaMemsetAsync(p_relnz, 0,    RR * sizeof(int));
    cudaMemsetAsync(p_fill,  0,    RR * sizeof(int));
    cudaMemsetAsync(p_bins,  0,    MAXBLK * sizeof(int));
    cudaMemsetAsync(p_vnode, 0xFF, NVROW * sizeof(int));
    cudaMemsetAsync(p_out,   0,    (size_t)NN * DD * sizeof(float));

    // ---- prep ----
    k_prep1<<<PREP1_GRID, T>>>(x_ids, emb, W1, root1, W2, root2, ei, et);
    k_inv_relnz<<<(NPAIR + T - 1) / T, T>>>();
    k_bases_blockrel<<<1, 1024>>>();
    k_compact<<<(NPAIR + T - 1) / T, T>>>();
    k_scan<<<1, 1024>>>();
    k_eperm<<<(EE + T - 1) / T, T>>>(ei, et);

    const int allBlocks = MAXBLK + ROOTBLK;   // rel blocks first, then root

    // ---- layer 1 ----
    k_gemm_all<<<allBlocks, 256, GSM_TOTAL>>>(0);
    k_act_relu<<<(NN * 32) / T, T>>>(b1);   // also zeroes g_out for layer 2

    // ---- layer 2 ----
    k_gemm_all<<<allBlocks, 256, GSM_TOTAL>>>(KT * DD);
    k_sigmoid<<<(NN * 32) / T, T>>>(b2, out);
}

// round 15
// speedup vs baseline: 2.5279x; 1.0113x over previous
#include <cuda_runtime.h>
#include <cuda_fp16.h>
#include <math.h>
#include <stdint.h>

// Problem constants
#define NN 100000      // nodes
#define EE 500000      // edges
#define RR 8           // relations
#define DD 128         // hidden
#define KT 1152        // Wt rows: R*D (relations) + D (root)
#define NPAIR (NN * RR)                     // 800000 (node, rel) pairs
#define TM 64                               // GEMM tile M (block granularity)
#define MAXBLK ((NPAIR + RR * (TM - 1) + TM - 1) / TM)   // max 64-row blocks after padding
#define NVROW (MAXBLK * TM)
#define ROOTBLK ((NN + TM - 1) / TM)        // 1563
#define GB 4                                // blocks per GEMM CTA (B-reuse loop)
#define RELCTA  ((MAXBLK + GB - 1) / GB)
#define ROOTCTA ((ROOTBLK + GB - 1) / GB)

// -------- scratch (device globals; no allocation allowed) --------
__device__ __half g_xh [(size_t)NN * DD];        // x (fp16)
__device__ __half g_wth[2 * (size_t)KT * DD];    // weights fp16, both layers
__device__ float g_out[(size_t)NN * DD];
__device__ float g_inv[NPAIR];       // 1/indeg(dst,rel)
__device__ int   g_cnt[NPAIR];       // in-degree per (dst,rel)
__device__ int   g_scnt[NPAIR];      // out-degree per (src,rel)
__device__ int   g_pos[NPAIR];       // (src,rel) -> virtual row
__device__ int   g_vnode[NVROW];     // virtual row -> node (-1 = pad)
__device__ int   g_relnz[RR];
__device__ int   g_fill[RR];
__device__ int   g_base[RR + 1];
__device__ int   g_nblk;             // active blocks
__device__ int   g_blockrel[MAXBLK];
__device__ int   g_bins[MAXBLK];
__device__ int   g_ptr[MAXBLK + 1];
__device__ int   g_cur[MAXBLK];
__device__ int   g_els[EE];          // sorted edges: local src row (pos % TM)
__device__ int   g_ed[EE];           // sorted edges: dst
__device__ float g_einv[EE];         // sorted edges: 1/cnt(dst,rel)

// ---------------- helpers ----------------
__device__ __forceinline__ uint32_t saddr(const void* p) {
    return (uint32_t)__cvta_generic_to_shared(p);
}
__device__ __forceinline__ void ldsm_x4(uint32_t* r, uint32_t addr) {
    asm volatile("ldmatrix.sync.aligned.m8n8.x4.shared.b16 {%0,%1,%2,%3}, [%4];"
                 : "=r"(r[0]), "=r"(r[1]), "=r"(r[2]), "=r"(r[3]) : "r"(addr));
}
__device__ __forceinline__ void mma_f16(float* c, const uint32_t* a, const uint32_t* b) {
    asm volatile("mma.sync.aligned.m16n8k16.row.col.f32.f16.f16.f32 "
                 "{%0,%1,%2,%3}, {%4,%5,%6,%7}, {%8,%9}, {%0,%1,%2,%3};"
                 : "+f"(c[0]), "+f"(c[1]), "+f"(c[2]), "+f"(c[3])
                 : "r"(a[0]), "r"(a[1]), "r"(a[2]), "r"(a[3]), "r"(b[0]), "r"(b[1]));
}
__device__ __forceinline__ void red_add4(float* p, float4 v) {
    asm volatile("red.global.add.v4.f32 [%0], {%1, %2, %3, %4};"
                 :: "l"(p), "f"(v.x), "f"(v.y), "f"(v.z), "f"(v.w) : "memory");
}
__device__ __forceinline__ void red_add2(float* p, float2 v) {
    asm volatile("red.global.add.v2.f32 [%0], {%1, %2};"
                 :: "l"(p), "f"(v.x), "f"(v.y) : "memory");
}
// 16B async copy; src_size = 16 (copy) or 0 (zero-fill, pad rows)
__device__ __forceinline__ void cp16(uint32_t dst, const void* src, int src_size) {
    asm volatile("cp.async.cg.shared.global [%0], [%1], 16, %2;"
                 :: "r"(dst), "l"(src), "r"(src_size) : "memory");
}
__device__ __forceinline__ void cp_commit_wait() {
    asm volatile("cp.async.commit_group;" ::: "memory");
    asm volatile("cp.async.wait_group 0;" ::: "memory");
}

// ---------------- fused prep: gather | wsplit(L1) | wsplit(L2) | hist2 ----------------
#define P_GATHER (NN * 32 / 256)                 // 12500 blocks
#define P_WS     ((KT * DD) / 256)               // 576 blocks each
#define P_HIST   ((EE + 255) / 256)              // 1954 blocks
#define PREP1_GRID (P_GATHER + 2 * P_WS + P_HIST)

__global__ void k_prep1(const int* __restrict__ ids, const float* __restrict__ emb,
                        const float* __restrict__ W1, const float* __restrict__ root1,
                        const float* __restrict__ W2, const float* __restrict__ root2,
                        const int* __restrict__ ei, const int* __restrict__ et) {
    int b = blockIdx.x;
    if (b < P_GATHER) {
        int t = b * 256 + threadIdx.x;
        int n = t >> 5, l4 = (t & 31) * 4;
        if (n >= NN) return;
        float4 v = *((const float4*)(emb + (size_t)ids[n] * DD + l4));
        __half2* ph = (__half2*)(g_xh + (size_t)n * DD + l4);
        ph[0] = __half2{__float2half(v.x), __float2half(v.y)};
        ph[1] = __half2{__float2half(v.z), __float2half(v.w)};
        return;
    }
    b -= P_GATHER;
    if (b < 2 * P_WS) {
        int layer = b >= P_WS;
        int t = (b - layer * P_WS) * 256 + threadIdx.x;
        const float* W     = layer ? W2 : W1;
        const float* rootM = layer ? root2 : root1;
        int loff = layer * KT * DD;
        int c = t >> 7, d = t & 127;
        float v;
        if (c < RR * DD) {
            int r = c >> 7, f = c & 127;
            v = W[((size_t)r * DD + d) * DD + f];
        } else {
            v = rootM[(size_t)d * DD + (c - RR * DD)];
        }
        g_wth[loff + t] = __float2half(v);
        return;
    }
    b -= 2 * P_WS;
    {
        int e = b * 256 + threadIdx.x;
        if (e >= EE) return;
        int src = ei[e], dst = ei[EE + e], r = et[e];
        atomicAdd(&g_cnt[dst * RR + r], 1);
        atomicAdd(&g_scnt[src * RR + r], 1);
    }
}

// inv + per-relation live-pair counts (block-aggregated atomics)
__global__ void k_inv_relnz() {
    __shared__ int c[RR];
    if (threadIdx.x < RR) c[threadIdx.x] = 0;
    __syncthreads();
    int t = blockIdx.x * blockDim.x + threadIdx.x;
    if (t < NPAIR) {
        int n = g_cnt[t];
        g_inv[t] = n > 0 ? 1.0f / (float)n : 0.0f;
        if (g_scnt[t] > 0) atomicAdd(&c[t & (RR - 1)], 1);
    }
    __syncthreads();
    if (threadIdx.x < RR && c[threadIdx.x] > 0) atomicAdd(&g_relnz[threadIdx.x], c[threadIdx.x]);
}

// bases (serial, 8 iters) + blockrel fill, single block
__global__ void k_bases_blockrel() {
    __shared__ int sbase[RR + 1];
    if (threadIdx.x == 0) {
        int b = 0;
        g_base[0] = 0; sbase[0] = 0;
        for (int r = 0; r < RR; r++) {
            b += (g_relnz[r] + TM - 1) & ~(TM - 1);
            g_base[r + 1] = b; sbase[r + 1] = b;
        }
        g_nblk = b / TM;
    }
    __syncthreads();
    for (int i = threadIdx.x; i < MAXBLK; i += blockDim.x) {
        int row = i * TM, rel = 0;
        for (int r = 0; r < RR; r++)
            if (row >= sbase[r] && row < sbase[r + 1]) rel = r;
        g_blockrel[i] = rel;
    }
}

// compact live pairs into virtual rows + per-block edge bin counts.
// Block-aggregated g_fill atomics: smem rank within block, ONE global
// atomicAdd per (block, relation).
__global__ void k_compact() {
    __shared__ int cnt[RR];
    __shared__ int basep[RR];
    int t = blockIdx.x * 256 + threadIdx.x;
    if (threadIdx.x < RR) cnt[threadIdx.x] = 0;
    __syncthreads();
    int sc = 0, rel = 0, rank = 0, node = 0;
    bool live = false;
    if (t < NPAIR) {
        sc = g_scnt[t];
        if (sc > 0) {
            live = true;
            node = t >> 3;              // RR == 8
            rel  = t & 7;
            rank = atomicAdd(&cnt[rel], 1);
        }
    }
    __syncthreads();
    if (threadIdx.x < RR)
        basep[threadIdx.x] = cnt[threadIdx.x] ? atomicAdd(&g_fill[threadIdx.x], cnt[threadIdx.x]) : 0;
    __syncthreads();
    if (live) {
        int pos = g_base[rel] + basep[rel] + rank;
        g_vnode[pos] = node;
        g_pos[t] = pos;
        atomicAdd(&g_bins[pos / TM], sc);   // bin size = sum of out-degrees
    }
}

// single-block exclusive scan over MAXBLK bins
__global__ void k_scan() {
    __shared__ int wsum[32];
    const int tid = threadIdx.x;
    const int per = (MAXBLK + 1023) / 1024;
    int base = tid * per;
    int loc[16]; int s = 0;
    for (int i = 0; i < per; i++) {
        int idx = base + i;
        int v = (idx < MAXBLK) ? g_bins[idx] : 0;
        loc[i] = s; s += v;
    }
    int lane = tid & 31, wid = tid >> 5;
    int x = s;
    for (int d = 1; d < 32; d <<= 1) {
        int y = __shfl_up_sync(0xffffffffu, x, d);
        if (lane >= d) x += y;
    }
    if (lane == 31) wsum[wid] = x;
    __syncthreads();
    if (wid == 0) {
        int y = wsum[lane];
        for (int d = 1; d < 32; d <<= 1) {
            int z = __shfl_up_sync(0xffffffffu, y, d);
            if (lane >= d) y += z;
        }
        wsum[lane] = y;
    }
    __syncthreads();
    int excl = x - s + (wid > 0 ? wsum[wid - 1] : 0);
    for (int i = 0; i < per; i++) {
        int idx = base + i;
        if (idx < MAXBLK) { int p = excl + loc[i]; g_ptr[idx] = p; g_cur[idx] = p; }
    }
    if (tid == 1023) g_ptr[MAXBLK] = excl + s;
}

__global__ void k_eperm(const int* __restrict__ ei, const int* __restrict__ et) {
    int e = blockIdx.x * blockDim.x + threadIdx.x;
    if (e >= EE) return;
    int src = ei[e], dst = ei[EE + e], r = et[e];
    int pos = g_pos[src * RR + r];
    int i = atomicAdd(&g_cur[pos / TM], 1);
    g_els[i]  = pos % TM;
    g_ed[i]   = dst;
    g_einv[i] = g_inv[dst * RR + r];
}

// ---------------- combined GEMM (rel CTAs first, then root CTAs) ----------------
// Each CTA processes GB consecutive 64-row blocks, reusing the B tile across
// blocks of the same relation (contiguous + TM-aligned by construction).
// h tile stored fp16 in the A region (A dead post-MMA) so B stays live at occ 4.
// g_out pre-zeroed; both paths accumulate via red.add.
#define PADK 136
#define GSM_A  0
#define GSM_B  17408
#define GSM_TOTAL 52224      // per-CTA dynamic smem; 4 CTAs/SM

// MMA core: 64(M) x 128(N) x 128(K), warps 2(M) x 4(N), warp tile 32x32
#define MMA_CORE(As, Bs, acc)                                                      \
    {                                                                              \
        _Pragma("unroll")                                                          \
        for (int ks = 0; ks < 8; ks++) {                                           \
            const int k0 = ks * 16;                                                \
            uint32_t ah[2][4];                                                     \
            _Pragma("unroll")                                                      \
            for (int mf = 0; mf < 2; mf++)                                         \
                ldsm_x4(ah[mf], saddr(As + (a_row + mf * 16) * PADK + k0 + a_koff));\
            _Pragma("unroll")                                                      \
            for (int np = 0; np < 2; np++) {                                       \
                uint32_t bh[4];                                                    \
                ldsm_x4(bh, saddr(Bs + (b_nrow + np * 16) * PADK + k0 + b_koff));  \
                _Pragma("unroll")                                                  \
                for (int sub = 0; sub < 2; sub++) {                                \
                    uint32_t bfh[2] = { bh[sub], bh[sub + 2] };                    \
                    _Pragma("unroll")                                              \
                    for (int mf = 0; mf < 2; mf++)                                 \
                        mma_f16(acc[mf][np * 2 + sub], ah[mf], bfh);               \
                }                                                                  \
            }                                                                      \
        }                                                                          \
    }

__global__ __launch_bounds__(256, 4)
void k_gemm_all(int loff) {
    extern __shared__ char sm[];
    __half* As  = (__half*)(sm + GSM_A);
    __half* Bs  = (__half*)(sm + GSM_B);
    __half* hsm = (__half*)(sm + GSM_A);   // fp16 h tile aliases A (16KB <= 17KB)

    const int tid  = threadIdx.x;
    const int lane = tid & 31, warp = tid >> 5;

    const bool isRel = (int)blockIdx.x < RELCTA;
    const int  base  = isRel ? (int)blockIdx.x * GB
                             : ((int)blockIdx.x - RELCTA) * GB;
    const int  limit = isRel ? g_nblk : ROOTBLK;
    if (base >= limit) return;   // uniform

    const int wm = warp & 1, wn = warp >> 1;
    const int a_row  = wm * 32 + (lane & 15);
    const int a_koff = (lane >> 4) * 8;
    const int b_nrow = wn * 32 + (lane & 7) + ((lane >> 3) & 1) * 8;
    const int b_koff = (lane >> 4) * 8;

    int loadedRel = -1;   // which B tile is resident (-2 = root tile)

    for (int g = 0; g < GB; g++) {
        const int blk = base + g;
        if (blk >= limit) break;              // uniform across CTA
        const int rel  = isRel ? g_blockrel[blk] : -2;
        const int row0 = blk * TM;

        // ---- async load A (and B if relation changed) ----
        if (rel != loadedRel) {
            const int brow = isRel ? rel : RR;
            for (int v = tid; v < 2048; v += 256) {
                int r = v >> 4, c8 = (v & 15) << 3;
                const size_t gofs = (size_t)loff + (size_t)(brow * DD + r) * DD + c8;
                cp16(saddr(Bs + r * PADK + c8), g_wth + gofs, 16);
            }
            loadedRel = rel;
        }
        for (int v = tid; v < 1024; v += 256) {
            int r = v >> 4, c8 = (v & 15) << 3;
            int node;
            if (isRel) node = g_vnode[row0 + r];
            else       node = (row0 + r < NN) ? row0 + r : -1;
            int sz = node >= 0 ? 16 : 0;
            size_t gofs = (size_t)(node >= 0 ? node : 0) * DD + c8;
            cp16(saddr(As + r * PADK + c8), g_xh + gofs, sz);
        }
        cp_commit_wait();
        __syncthreads();

        float acc[2][4][4];
#pragma unroll
        for (int i = 0; i < 2; i++)
#pragma unroll
            for (int j = 0; j < 4; j++)
#pragma unroll
                for (int k = 0; k < 4; k++) acc[i][j][k] = 0.f;

        MMA_CORE(As, Bs, acc)

        __syncthreads();   // all warps done reading A before hsm/next-A overwrites it

        if (!isRel) {
            // root path: accumulate into pre-zeroed g_out
#pragma unroll
            for (int mf = 0; mf < 2; mf++) {
#pragma unroll
                for (int nf = 0; nf < 4; nf++) {
                    int r = row0 + wm * 32 + mf * 16 + (lane >> 2);
                    int c = wn * 32 + nf * 8 + (lane & 3) * 2;
                    float* cc = acc[mf][nf];
                    if (r < NN)
                        red_add2(g_out + (size_t)r * DD + c, make_float2(cc[0], cc[1]));
                    if (r + 8 < NN)
                        red_add2(g_out + (size_t)(r + 8) * DD + c, make_float2(cc[2], cc[3]));
                }
            }
            continue;   // next block (A overwrite is safe: sync above)
        }

        // h tile -> smem as fp16 (aliased over A)
#pragma unroll
        for (int mf = 0; mf < 2; mf++) {
#pragma unroll
            for (int nf = 0; nf < 4; nf++) {
                int r = wm * 32 + mf * 16 + (lane >> 2);
                int c = wn * 32 + nf * 8 + (lane & 3) * 2;
                float* cc = acc[mf][nf];
                *(__half2*)(hsm + r * 128 + c) =
                    __half2{__float2half(cc[0]), __float2half(cc[1])};
                *(__half2*)(hsm + (r + 8) * 128 + c) =
                    __half2{__float2half(cc[2]), __float2half(cc[3])};
            }
        }
        __syncthreads();

        // scatter this block's edges (one warp per edge; lane owns 4 cols)
        int s = g_ptr[blk], e2 = g_ptr[blk + 1];
        for (int i = s + warp; i < e2; i += 8) {
            int   ls  = g_els[i];
            int   dst = g_ed[i];
            float inv = g_einv[i];
            __half2 p0 = *(const __half2*)(hsm + ls * 128 + lane * 4);
            __half2 p1 = *(const __half2*)(hsm + ls * 128 + lane * 4 + 2);
            float2 f0 = __half22float2(p0);
            float2 f1 = __half22float2(p1);
            float4 v = make_float4(f0.x * inv, f0.y * inv, f1.x * inv, f1.y * inv);
            red_add4(g_out + (size_t)dst * DD + lane * 4, v);
        }
        __syncthreads();   // scatter done before next iteration overwrites hsm/A
    }
}

// ---------------- activations ----------------
// relu + fp16 convert; ALSO zeroes g_out in the same pass (replaces the L2 memset)
__global__ void k_act_relu(const float* __restrict__ bias) {
    int t = blockIdx.x * blockDim.x + threadIdx.x;
    if (t >= NN * 32) return;
    float4 v = *(const float4*)(g_out + (size_t)t * 4);
    float4 b = __ldg((const float4*)(bias + (t & 31) * 4));
    v.x = fmaxf(v.x + b.x, 0.f); v.y = fmaxf(v.y + b.y, 0.f);
    v.z = fmaxf(v.z + b.z, 0.f); v.w = fmaxf(v.w + b.w, 0.f);
    *(float4*)(g_out + (size_t)t * 4) = make_float4(0.f, 0.f, 0.f, 0.f);
    __half2* ph = (__half2*)(g_xh + (size_t)t * 4);
    ph[0] = __half2{__float2half(v.x), __float2half(v.y)};
    ph[1] = __half2{__float2half(v.z), __float2half(v.w)};
}

__global__ void k_sigmoid(const float* __restrict__ bias, float* __restrict__ outp) {
    int t = blockIdx.x * blockDim.x + threadIdx.x;
    if (t >= NN * 32) return;
    float4 v = *(const float4*)(g_out + (size_t)t * 4);
    float4 b = __ldg((const float4*)(bias + (t & 31) * 4));
    v.x = 1.0f / (1.0f + __expf(-(v.x + b.x)));
    v.y = 1.0f / (1.0f + __expf(-(v.y + b.y)));
    v.z = 1.0f / (1.0f + __expf(-(v.z + b.z)));
    v.w = 1.0f / (1.0f + __expf(-(v.w + b.w)));
    *(float4*)(outp + (size_t)t * 4) = v;
}

// ---------------- launch ----------------
extern "C" void kernel_launch(void* const* d_in, const int* in_sizes, int n_in,
                              void* d_out, int out_size) {
    const int*   x_ids = (const int*)  d_in[0];
    const int*   ei    = (const int*)  d_in[1];   // [2, E]: src row then dst row
    const int*   et    = (const int*)  d_in[2];
    const float* emb   = (const float*)d_in[3];
    const float* W1    = (const float*)d_in[4];
    const float* root1 = (const float*)d_in[5];
    const float* b1    = (const float*)d_in[6];
    const float* W2    = (const float*)d_in[7];
    const float* root2 = (const float*)d_in[8];
    const float* b2    = (const float*)d_in[9];
    float*       out   = (float*)d_out;
    (void)in_sizes; (void)n_in; (void)out_size;

    cudaFuncSetAttribute(k_gemm_all, cudaFuncAttributeMaxDynamicSharedMemorySize, GSM_TOTAL);

    void *p_cnt, *p_scnt, *p_relnz, *p_fill, *p_bins, *p_vnode, *p_out;
    cudaGetSymbolAddress(&p_cnt,   g_cnt);
    cudaGetSymbolAddress(&p_scnt,  g_scnt);
    cudaGetSymbolAddress(&p_relnz, g_relnz);
    cudaGetSymbolAddress(&p_fill,  g_fill);
    cudaGetSymbolAddress(&p_bins,  g_bins);
    cudaGetSymbolAddress(&p_vnode, g_vnode);
    cudaGetSymbolAddress(&p_out,   g_out);

    const int T = 256;

    // ---- zero/init (async memsets; g_vnode = 0xFF.. == -1) ----
    cudaMemsetAsync(p_cnt,   0,    NPAIR * sizeof(int));
    cudaMemsetAsync(p_scnt,  0,    NPAIR * sizeof(int));
    cudaMemsetAsync(p_relnz, 0,    RR * sizeof(int));
    cudaMemsetAsync(p_fill,  0,    RR * sizeof(int));
    cudaMemsetAsync(p_bins,  0,    MAXBLK * sizeof(int));
    cudaMemsetAsync(p_vnode, 0xFF, NVROW * sizeof(int));
    cudaMemsetAsync(p_out,   0,    (size_t)NN * DD * sizeof(float));

    // ---- prep ----
    k_prep1<<<PREP1_GRID, T>>>(x_ids, emb, W1, root1, W2, root2, ei, et);
    k_inv_relnz<<<(NPAIR + T - 1) / T, T>>>();
    k_bases_blockrel<<<1, 1024>>>();
    k_compact<<<(NPAIR + T - 1) / T, T>>>();
    k_scan<<<1, 1024>>>();
    k_eperm<<<(EE + T - 1) / T, T>>>(ei, et);

    const int allBlocks = RELCTA + ROOTCTA;   // rel CTAs first, then root CTAs

    // ---- layer 1 ----
    k_gemm_all<<<allBlocks, 256, GSM_TOTAL>>>(0);
    k_act_relu<<<(NN * 32) / T, T>>>(b1);   // also zeroes g_out for layer 2

    // ---- layer 2 ----
    k_gemm_all<<<allBlocks, 256, GSM_TOTAL>>>(KT * DD);
    k_sigmoid<<<(NN * 32) / T, T>>>(b2, out);
}

// round 17
// speedup vs baseline: 2.7111x; 1.0725x over previous
#include <cuda_runtime.h>
#include <cuda_fp16.h>
#include <math.h>
#include <stdint.h>

// Problem constants
#define NN 100000      // nodes
#define EE 500000      // edges
#define RR 8           // relations
#define DD 128         // hidden
#define KT 1152        // Wt rows: R*D (relations) + D (root)
#define NPAIR (NN * RR)                     // 800000 (node, rel) pairs
#define TM 64                               // GEMM tile M (block granularity)
#define MAXBLK ((NPAIR + RR * (TM - 1) + TM - 1) / TM)   // max 64-row blocks after padding
#define NVROW (MAXBLK * TM)
#define ROOTBLK ((NN + TM - 1) / TM)        // 1563
#define GB 4                                // blocks per GEMM CTA
#define RELCTA  ((MAXBLK + GB - 1) / GB)
#define ROOTCTA ((ROOTBLK + GB - 1) / GB)

// -------- scratch (device globals; no allocation allowed) --------
__device__ __half g_xh [(size_t)NN * DD];        // x (fp16)
__device__ __half g_wth[2 * (size_t)KT * DD];    // weights fp16, both layers
__device__ float g_out[(size_t)NN * DD];
__device__ float g_inv[NPAIR];       // 1/indeg(dst,rel)
__device__ int   g_cnt[NPAIR];       // in-degree per (dst,rel)
__device__ int   g_scnt[NPAIR];      // out-degree per (src,rel)
__device__ int   g_pos[NPAIR];       // (src,rel) -> virtual row
__device__ int   g_vnode[NVROW];     // virtual row -> node (-1 = pad)
__device__ int   g_relnz[RR];
__device__ int   g_fill[RR];
__device__ int   g_base[RR + 1];     // written by k_compact block 0
__device__ int   g_nblk;             // active rel blocks
__device__ int   g_bins[MAXBLK];
__device__ int   g_ptr[MAXBLK + 1];
__device__ int   g_cur[MAXBLK];
__device__ int   g_els[EE];          // sorted edges: local src row (pos % TM)
__device__ int   g_ed[EE];           // sorted edges: dst
__device__ float g_einv[EE];         // sorted edges: 1/cnt(dst,rel)

// ---------------- helpers ----------------
__device__ __forceinline__ uint32_t saddr(const void* p) {
    return (uint32_t)__cvta_generic_to_shared(p);
}
__device__ __forceinline__ void ldsm_x4(uint32_t* r, uint32_t addr) {
    asm volatile("ldmatrix.sync.aligned.m8n8.x4.shared.b16 {%0,%1,%2,%3}, [%4];"
                 : "=r"(r[0]), "=r"(r[1]), "=r"(r[2]), "=r"(r[3]) : "r"(addr));
}
__device__ __forceinline__ void mma_f16(float* c, const uint32_t* a, const uint32_t* b) {
    asm volatile("mma.sync.aligned.m16n8k16.row.col.f32.f16.f16.f32 "
                 "{%0,%1,%2,%3}, {%4,%5,%6,%7}, {%8,%9}, {%0,%1,%2,%3};"
                 : "+f"(c[0]), "+f"(c[1]), "+f"(c[2]), "+f"(c[3])
                 : "r"(a[0]), "r"(a[1]), "r"(a[2]), "r"(a[3]), "r"(b[0]), "r"(b[1]));
}
__device__ __forceinline__ void red_add4(float* p, float4 v) {
    asm volatile("red.global.add.v4.f32 [%0], {%1, %2, %3, %4};"
                 :: "l"(p), "f"(v.x), "f"(v.y), "f"(v.z), "f"(v.w) : "memory");
}
// 16B async copy; src_size = 16 (copy) or 0 (zero-fill, pad rows)
__device__ __forceinline__ void cp16(uint32_t dst, const void* src, int src_size) {
    asm volatile("cp.async.cg.shared.global [%0], [%1], 16, %2;"
                 :: "r"(dst), "l"(src), "r"(src_size) : "memory");
}
__device__ __forceinline__ void cp_commit_wait() {
    asm volatile("cp.async.commit_group;" ::: "memory");
    asm volatile("cp.async.wait_group 0;" ::: "memory");
}

// ---------------- fused prep: gather | wsplit(L1) | wsplit(L2) | hist2 ----------------
#define P_GATHER (NN * 32 / 256)                 // 12500 blocks
#define P_WS     ((KT * DD) / 256)               // 576 blocks each
#define P_HIST   ((EE + 255) / 256)              // 1954 blocks
#define PREP1_GRID (P_GATHER + 2 * P_WS + P_HIST)

__global__ void k_prep1(const int* __restrict__ ids, const float* __restrict__ emb,
                        const float* __restrict__ W1, const float* __restrict__ root1,
                        const float* __restrict__ W2, const float* __restrict__ root2,
                        const int* __restrict__ ei, const int* __restrict__ et) {
    int b = blockIdx.x;
    if (b < P_GATHER) {
        int t = b * 256 + threadIdx.x;
        int n = t >> 5, l4 = (t & 31) * 4;
        if (n >= NN) return;
        float4 v = *((const float4*)(emb + (size_t)ids[n] * DD + l4));
        __half2* ph = (__half2*)(g_xh + (size_t)n * DD + l4);
        ph[0] = __half2{__float2half(v.x), __float2half(v.y)};
        ph[1] = __half2{__float2half(v.z), __float2half(v.w)};
        return;
    }
    b -= P_GATHER;
    if (b < 2 * P_WS) {
        int layer = b >= P_WS;
        int t = (b - layer * P_WS) * 256 + threadIdx.x;
        const float* W     = layer ? W2 : W1;
        const float* rootM = layer ? root2 : root1;
        int loff = layer * KT * DD;
        int c = t >> 7, d = t & 127;
        float v;
        if (c < RR * DD) {
            int r = c >> 7, f = c & 127;
            v = W[((size_t)r * DD + d) * DD + f];
        } else {
            v = rootM[(size_t)d * DD + (c - RR * DD)];
        }
        g_wth[loff + t] = __float2half(v);
        return;
    }
    b -= 2 * P_WS;
    {
        int e = b * 256 + threadIdx.x;
        if (e >= EE) return;
        int src = ei[e], dst = ei[EE + e], r = et[e];
        atomicAdd(&g_cnt[dst * RR + r], 1);
        atomicAdd(&g_scnt[src * RR + r], 1);
    }
}

// inv + per-relation live-pair counts (block-aggregated atomics)
__global__ void k_inv_relnz() {
    __shared__ int c[RR];
    if (threadIdx.x < RR) c[threadIdx.x] = 0;
    __syncthreads();
    int t = blockIdx.x * blockDim.x + threadIdx.x;
    if (t < NPAIR) {
        int n = g_cnt[t];
        g_inv[t] = n > 0 ? 1.0f / (float)n : 0.0f;
        if (g_scnt[t] > 0) atomicAdd(&c[t & (RR - 1)], 1);
    }
    __syncthreads();
    if (threadIdx.x < RR && c[threadIdx.x] > 0) atomicAdd(&g_relnz[threadIdx.x], c[threadIdx.x]);
}

// compact live pairs into virtual rows + per-block edge bin counts.
// Each block recomputes the TM-padded relation bases from g_relnz locally
// (pure function, 8 values); block 0 publishes g_base / g_nblk for the GEMM.
__global__ void k_compact() {
    __shared__ int sbase[RR + 1];
    __shared__ int cnt[RR];
    __shared__ int basep[RR];
    if (threadIdx.x == 0) {
        int b = 0;
        sbase[0] = 0;
        for (int r = 0; r < RR; r++) {
            b += (g_relnz[r] + TM - 1) & ~(TM - 1);
            sbase[r + 1] = b;
        }
        if (blockIdx.x == 0) {
            for (int r = 0; r <= RR; r++) g_base[r] = sbase[r];
            g_nblk = b / TM;
        }
    }
    if (threadIdx.x < RR) cnt[threadIdx.x] = 0;
    __syncthreads();
    int t = blockIdx.x * 256 + threadIdx.x;
    int sc = 0, rel = 0, rank = 0, node = 0;
    bool live = false;
    if (t < NPAIR) {
        sc = g_scnt[t];
        if (sc > 0) {
            live = true;
            node = t >> 3;              // RR == 8
            rel  = t & 7;
            rank = atomicAdd(&cnt[rel], 1);
        }
    }
    __syncthreads();
    if (threadIdx.x < RR)
        basep[threadIdx.x] = cnt[threadIdx.x] ? atomicAdd(&g_fill[threadIdx.x], cnt[threadIdx.x]) : 0;
    __syncthreads();
    if (live) {
        int pos = sbase[rel] + basep[rel] + rank;
        g_vnode[pos] = node;
        g_pos[t] = pos;
        atomicAdd(&g_bins[pos / TM], sc);   // bin size = sum of out-degrees
    }
}

// single-block exclusive scan over MAXBLK bins
__global__ void k_scan() {
    __shared__ int wsum[32];
    const int tid = threadIdx.x;
    const int per = (MAXBLK + 1023) / 1024;
    int base = tid * per;
    int loc[16]; int s = 0;
    for (int i = 0; i < per; i++) {
        int idx = base + i;
        int v = (idx < MAXBLK) ? g_bins[idx] : 0;
        loc[i] = s; s += v;
    }
    int lane = tid & 31, wid = tid >> 5;
    int x = s;
    for (int d = 1; d < 32; d <<= 1) {
        int y = __shfl_up_sync(0xffffffffu, x, d);
        if (lane >= d) x += y;
    }
    if (lane == 31) wsum[wid] = x;
    __syncthreads();
    if (wid == 0) {
        int y = wsum[lane];
        for (int d = 1; d < 32; d <<= 1) {
            int z = __shfl_up_sync(0xffffffffu, y, d);
            if (lane >= d) y += z;
        }
        wsum[lane] = y;
    }
    __syncthreads();
    int excl = x - s + (wid > 0 ? wsum[wid - 1] : 0);
    for (int i = 0; i < per; i++) {
        int idx = base + i;
        if (idx < MAXBLK) { int p = excl + loc[i]; g_ptr[idx] = p; g_cur[idx] = p; }
    }
    if (tid == 1023) g_ptr[MAXBLK] = excl + s;
}

__global__ void k_eperm(const int* __restrict__ ei, const int* __restrict__ et) {
    int e = blockIdx.x * blockDim.x + threadIdx.x;
    if (e >= EE) return;
    int src = ei[e], dst = ei[EE + e], r = et[e];
    int pos = g_pos[src * RR + r];
    int i = atomicAdd(&g_cur[pos / TM], 1);
    g_els[i]  = pos % TM;
    g_ed[i]   = dst;
    g_einv[i] = g_inv[dst * RR + r];
}

// ---------------- GEMM kernels ----------------
#define PADK 136
#define GSM_A  0
#define GSM_B  17408
#define GSM_TOTAL 52224      // per-CTA dynamic smem; 4 CTAs/SM

// MMA core: 64(M) x 128(N) x 128(K), warps 2(M) x 4(N), warp tile 32x32
#define MMA_CORE(As, Bs, acc)                                                      \
    {                                                                              \
        _Pragma("unroll")                                                          \
        for (int ks = 0; ks < 8; ks++) {                                           \
            const int k0 = ks * 16;                                                \
            uint32_t ah[2][4];                                                     \
            _Pragma("unroll")                                                      \
            for (int mf = 0; mf < 2; mf++)                                         \
                ldsm_x4(ah[mf], saddr(As + (a_row + mf * 16) * PADK + k0 + a_koff));\
            _Pragma("unroll")                                                      \
            for (int np = 0; np < 2; np++) {                                       \
                uint32_t bh[4];                                                    \
                ldsm_x4(bh, saddr(Bs + (b_nrow + np * 16) * PADK + k0 + b_koff));  \
                _Pragma("unroll")                                                  \
                for (int sub = 0; sub < 2; sub++) {                                \
                    uint32_t bfh[2] = { bh[sub], bh[sub + 2] };                    \
                    _Pragma("unroll")                                              \
                    for (int mf = 0; mf < 2; mf++)                                 \
                        mma_f16(acc[mf][np * 2 + sub], ah[mf], bfh);               \
                }                                                                  \
            }                                                                      \
        }                                                                          \
    }

// root GEMM: g_out[n,:] = x[n,:] @ root (PLAIN STORE). Launched BEFORE k_gemm_rel;
// stream order makes the rel kernel's red.add accumulate on top. No memset needed.
__global__ __launch_bounds__(256, 4)
void k_gemm_root(int loff) {
    extern __shared__ char sm[];
    __half* As = (__half*)(sm + GSM_A);
    __half* Bs = (__half*)(sm + GSM_B);

    const int tid  = threadIdx.x;
    const int lane = tid & 31, warp = tid >> 5;
    const int base = (int)blockIdx.x * GB;
    if (base >= ROOTBLK) return;

    const int wm = warp & 1, wn = warp >> 1;
    const int a_row  = wm * 32 + (lane & 15);
    const int a_koff = (lane >> 4) * 8;
    const int b_nrow = wn * 32 + (lane & 7) + ((lane >> 3) & 1) * 8;
    const int b_koff = (lane >> 4) * 8;

    // B (root tile) loaded once — shared by all GB blocks
    for (int v = tid; v < 2048; v += 256) {
        int r = v >> 4, c8 = (v & 15) << 3;
        const size_t gofs = (size_t)loff + (size_t)(RR * DD + r) * DD + c8;
        cp16(saddr(Bs + r * PADK + c8), g_wth + gofs, 16);
    }

    for (int g = 0; g < GB; g++) {
        const int blk = base + g;
        if (blk >= ROOTBLK) break;
        const int row0 = blk * TM;

        for (int v = tid; v < 1024; v += 256) {
            int r = v >> 4, c8 = (v & 15) << 3;
            int node = (row0 + r < NN) ? row0 + r : -1;
            int sz = node >= 0 ? 16 : 0;
            size_t gofs = (size_t)(node >= 0 ? node : 0) * DD + c8;
            cp16(saddr(As + r * PADK + c8), g_xh + gofs, sz);
        }
        cp_commit_wait();
        __syncthreads();

        float acc[2][4][4];
#pragma unroll
        for (int i = 0; i < 2; i++)
#pragma unroll
            for (int j = 0; j < 4; j++)
#pragma unroll
                for (int k = 0; k < 4; k++) acc[i][j][k] = 0.f;

        MMA_CORE(As, Bs, acc)

        __syncthreads();   // A dead before next iteration's load

#pragma unroll
        for (int mf = 0; mf < 2; mf++) {
#pragma unroll
            for (int nf = 0; nf < 4; nf++) {
                int r = row0 + wm * 32 + mf * 16 + (lane >> 2);
                int c = wn * 32 + nf * 8 + (lane & 3) * 2;
                float* cc = acc[mf][nf];
                if (r < NN)
                    *(float2*)(g_out + (size_t)r * DD + c) = make_float2(cc[0], cc[1]);
                if (r + 8 < NN)
                    *(float2*)(g_out + (size_t)(r + 8) * DD + c) = make_float2(cc[2], cc[3]);
            }
        }
    }
}

// rel GEMM + fused scatter. red.add on top of root-stored g_out.
// Each CTA processes GB consecutive blocks, reusing B across same-relation blocks.
// h tile stored fp16 in the A region (A dead post-MMA) so B stays live at occ 4.
__global__ __launch_bounds__(256, 4)
void k_gemm_rel(int loff) {
    extern __shared__ char sm[];
    __half* As  = (__half*)(sm + GSM_A);
    __half* Bs  = (__half*)(sm + GSM_B);
    __half* hsm = (__half*)(sm + GSM_A);   // fp16 h tile aliases A (16KB <= 17KB)

    const int tid  = threadIdx.x;
    const int lane = tid & 31, warp = tid >> 5;
    const int base = (int)blockIdx.x * GB;
    const int limit = g_nblk;
    if (base >= limit) return;

    const int wm = warp & 1, wn = warp >> 1;
    const int a_row  = wm * 32 + (lane & 15);
    const int a_koff = (lane >> 4) * 8;
    const int b_nrow = wn * 32 + (lane & 7) + ((lane >> 3) & 1) * 8;
    const int b_koff = (lane >> 4) * 8;

    int loadedRel = -1;

    for (int g = 0; g < GB; g++) {
        const int blk = base + g;
        if (blk >= limit) break;              // uniform across CTA
        // derive relation from g_base (blocks of one relation are contiguous)
        const int row0 = blk * TM;
        int rel = 0;
#pragma unroll
        for (int r = 1; r < RR; r++)
            if (row0 >= g_base[r]) rel = r;

        if (rel != loadedRel) {
            for (int v = tid; v < 2048; v += 256) {
                int r = v >> 4, c8 = (v & 15) << 3;
                const size_t gofs = (size_t)loff + (size_t)(rel * DD + r) * DD + c8;
                cp16(saddr(Bs + r * PADK + c8), g_wth + gofs, 16);
            }
            loadedRel = rel;
        }
        for (int v = tid; v < 1024; v += 256) {
            int r = v >> 4, c8 = (v & 15) << 3;
            int node = g_vnode[row0 + r];
            int sz = node >= 0 ? 16 : 0;
            size_t gofs = (size_t)(node >= 0 ? node : 0) * DD + c8;
            cp16(saddr(As + r * PADK + c8), g_xh + gofs, sz);
        }
        cp_commit_wait();
        __syncthreads();

        float acc[2][4][4];
#pragma unroll
        for (int i = 0; i < 2; i++)
#pragma unroll
            for (int j = 0; j < 4; j++)
#pragma unroll
                for (int k = 0; k < 4; k++) acc[i][j][k] = 0.f;

        MMA_CORE(As, Bs, acc)

        __syncthreads();   // all warps done reading A before hsm overwrites it

        // h tile -> smem as fp16 (aliased over A)
#pragma unroll
        for (int mf = 0; mf < 2; mf++) {
#pragma unroll
            for (int nf = 0; nf < 4; nf++) {
                int r = wm * 32 + mf * 16 + (lane >> 2);
                int c = wn * 32 + nf * 8 + (lane & 3) * 2;
                float* cc = acc[mf][nf];
                *(__half2*)(hsm + r * 128 + c) =
                    __half2{__float2half(cc[0]), __float2half(cc[1])};
                *(__half2*)(hsm + (r + 8) * 128 + c) =
                    __half2{__float2half(cc[2]), __float2half(cc[3])};
            }
        }
        __syncthreads();

        // scatter this block's edges (one warp per edge; lane owns 4 cols)
        int s = g_ptr[blk], e2 = g_ptr[blk + 1];
        for (int i = s + warp; i < e2; i += 8) {
            int   ls  = g_els[i];
            int   dst = g_ed[i];
            float inv = g_einv[i];
            __half2 p0 = *(const __half2*)(hsm + ls * 128 + lane * 4);
            __half2 p1 = *(const __half2*)(hsm + ls * 128 + lane * 4 + 2);
            float2 f0 = __half22float2(p0);
            float2 f1 = __half22float2(p1);
            float4 v = make_float4(f0.x * inv, f0.y * inv, f1.x * inv, f1.y * inv);
            red_add4(g_out + (size_t)dst * DD + lane * 4, v);
        }
        __syncthreads();   // scatter done before next iteration overwrites hsm/A
    }
}

// ---------------- activations ----------------
// relu + fp16 convert (no zeroing needed anymore — root kernel stores)
__global__ void k_act_relu(const float* __restrict__ bias) {
    int t = blockIdx.x * blockDim.x + threadIdx.x;
    if (t >= NN * 32) return;
    float4 v = *(const float4*)(g_out + (size_t)t * 4);
    float4 b = __ldg((const float4*)(bias + (t & 31) * 4));
    v.x = fmaxf(v.x + b.x, 0.f); v.y = fmaxf(v.y + b.y, 0.f);
    v.z = fmaxf(v.z + b.z, 0.f); v.w = fmaxf(v.w + b.w, 0.f);
    __half2* ph = (__half2*)(g_xh + (size_t)t * 4);
    ph[0] = __half2{__float2half(v.x), __float2half(v.y)};
    ph[1] = __half2{__float2half(v.z), __float2half(v.w)};
}

__global__ void k_sigmoid(const float* __restrict__ bias, float* __restrict__ outp) {
    int t = blockIdx.x * blockDim.x + threadIdx.x;
    if (t >= NN * 32) return;
    float4 v = *(const float4*)(g_out + (size_t)t * 4);
    float4 b = __ldg((const float4*)(bias + (t & 31) * 4));
    v.x = 1.0f / (1.0f + __expf(-(v.x + b.x)));
    v.y = 1.0f / (1.0f + __expf(-(v.y + b.y)));
    v.z = 1.0f / (1.0f + __expf(-(v.z + b.z)));
    v.w = 1.0f / (1.0f + __expf(-(v.w + b.w)));
    *(float4*)(outp + (size_t)t * 4) = v;
}

// ---------------- launch ----------------
extern "C" void kernel_launch(void* const* d_in, const int* in_sizes, int n_in,
                              void* d_out, int out_size) {
    const int*   x_ids = (const int*)  d_in[0];
    const int*   ei    = (const int*)  d_in[1];   // [2, E]: src row then dst row
    const int*   et    = (const int*)  d_in[2];
    const float* emb   = (const float*)d_in[3];
    const float* W1    = (const float*)d_in[4];
    const float* root1 = (const float*)d_in[5];
    const float* b1    = (const float*)d_in[6];
    const float* W2    = (const float*)d_in[7];
    const float* root2 = (const float*)d_in[8];
    const float* b2    = (const float*)d_in[9];
    float*       out   = (float*)d_out;
    (void)in_sizes; (void)n_in; (void)out_size;

    cudaFuncSetAttribute(k_gemm_root, cudaFuncAttributeMaxDynamicSharedMemorySize, GSM_TOTAL);
    cudaFuncSetAttribute(k_gemm_rel,  cudaFuncAttributeMaxDynamicSharedMemorySize, GSM_TOTAL);

    void *p_cnt, *p_scnt, *p_relnz, *p_fill, *p_bins, *p_vnode;
    cudaGetSymbolAddress(&p_cnt,   g_cnt);
    cudaGetSymbolAddress(&p_scnt,  g_scnt);
    cudaGetSymbolAddress(&p_relnz, g_relnz);
    cudaGetSymbolAddress(&p_fill,  g_fill);
    cudaGetSymbolAddress(&p_bins,  g_bins);
    cudaGetSymbolAddress(&p_vnode, g_vnode);

    const int T = 256;

    // ---- zero/init (async memsets; g_vnode = 0xFF.. == -1; g_out NOT zeroed) ----
    cudaMemsetAsync(p_cnt,   0,    NPAIR * sizeof(int));
    cudaMemsetAsync(p_scnt,  0,    NPAIR * sizeof(int));
    cudaMemsetAsync(p_relnz, 0,    RR * sizeof(int));
    cudaMemsetAsync(p_fill,  0,    RR * sizeof(int));
    cudaMemsetAsync(p_bins,  0,    MAXBLK * sizeof(int));
    cudaMemsetAsync(p_vnode, 0xFF, NVROW * sizeof(int));

    // ---- prep ----
    k_prep1<<<PREP1_GRID, T>>>(x_ids, emb, W1, root1, W2, root2, ei, et);
    // root GEMM L1 depends only on prep1 — issue immediately
    k_gemm_root<<<ROOTCTA, 256, GSM_TOTAL>>>(0);
    k_inv_relnz<<<(NPAIR + T - 1) / T, T>>>();
    k_compact<<<(NPAIR + T - 1) / T, T>>>();
    k_scan<<<1, 1024>>>();
    k_eperm<<<(EE + T - 1) / T, T>>>(ei, et);

    // ---- layer 1 ----
    k_gemm_rel<<<RELCTA, 256, GSM_TOTAL>>>(0);       // adds on top of root stores
    k_act_relu<<<(NN * 32) / T, T>>>(b1);

    // ---- layer 2 ----
    k_gemm_root<<<ROOTCTA, 256, GSM_TOTAL>>>(KT * DD);   // stores (L1 g_out is dead)
    k_gemm_rel<<<RELCTA, 256, GSM_TOTAL>>>(KT * DD);     // adds
    k_sigmoid<<<(NN * 32) / T, T>>>(b2, out);
}